// round 11
// baseline (speedup 1.0000x reference)
#include <cuda_runtime.h>
#include <cuda_fp16.h>
#include <math.h>
#include <stdint.h>

// Problem constants
#define Tt  2048
#define Bb  2
#define Ee  1024
#define Hh  16
#define HDd 64
#define BH  32          // Bb*Hh
#define MR  4096        // Tt*Bb rows

// -------- device scratch (allocation-free: static device globals) ----------
__device__ __align__(16) __half g_xh[3][(size_t)MR * Ee];    // 24 MB fp16 q/k/v inputs
__device__ __align__(16) __half g_wh[(size_t)3 * Ee * Ee];   //  6 MB fp16 in_proj_w
__device__ __align__(16) __half g_owh[(size_t)Ee * Ee];      //  2 MB fp16 out_w
__device__ __align__(16) __half g_qh[(size_t)BH * Tt * HDd]; //  8 MB (bh,t,hd), q*0.125
__device__ __align__(16) __half g_kh[(size_t)BH * Tt * HDd]; //  8 MB
__device__ __align__(16) __half g_vth[(size_t)BH * HDd * Tt];//  8 MB (bh,hd,t)
__device__ __align__(16) __half g_sh[(size_t)BH * Tt * Tt];  // 256 MB unnormalized exp(scores)
__device__ __align__(16) __half g_aoh[(size_t)MR * Ee];      //  8 MB rows = t*B+b
__device__            float  g_rinv[(size_t)BH * Tt];        // 1/rowsum

// ============================================================================
// fp16 mma m16n8k16 + ldmatrix helpers
// ============================================================================
__device__ __forceinline__ void mma16(float c[4], const uint32_t a[4],
                                      uint32_t b0, uint32_t b1) {
    asm volatile(
        "mma.sync.aligned.m16n8k16.row.col.f32.f16.f16.f32 "
        "{%0,%1,%2,%3}, {%4,%5,%6,%7}, {%8,%9}, {%0,%1,%2,%3};"
        : "+f"(c[0]), "+f"(c[1]), "+f"(c[2]), "+f"(c[3])
        : "r"(a[0]), "r"(a[1]), "r"(a[2]), "r"(a[3]), "r"(b0), "r"(b1));
}
__device__ __forceinline__ void ldsm4(uint32_t r[4], uint32_t addr) {
    asm volatile("ldmatrix.sync.aligned.m8n8.x4.shared.b16 {%0,%1,%2,%3}, [%4];"
        : "=r"(r[0]), "=r"(r[1]), "=r"(r[2]), "=r"(r[3]) : "r"(addr));
}

// ============================================================================
// NT fp16 tensor-core GEMM core, ping-pong smem (ONE __syncthreads per chunk).
//   C[m,n] += sum_k A[m,k] * B[n,k]   (both K-contiguous row-major, fp16)
// Block 256 thr (8 warps, 4x2). Block tile 128 x BN (64|128). Warp 32 x BN/2.
// K chunked by 32 halves. sA holds 2 buffers of 128*40 halves, sB 2 of BN*40.
// ============================================================================
template<int BN>
__device__ __forceinline__ void gemm_nt_f16(
    const __half* __restrict__ A, const __half* __restrict__ B,
    int lda, int ldb, int K, __half* sA, __half* sB,
    float acc[2][BN / 16][4])
{
    constexpr int NT   = BN / 16;
    constexpr int NJJ  = BN / 32;
    constexpr int P    = 40;
    constexpr int BPASS = BN / 64;
    constexpr int ABUFH = 128 * P;            // halves per A buffer
    constexpr int BBUFH = BN * P;

    const int tid = threadIdx.x, lane = tid & 31;
    const int w = tid >> 5, wm = w & 3, wn = w >> 2;
    const int lr = lane & 7, sel = lane >> 3;

    const uint32_t sAu = (uint32_t)__cvta_generic_to_shared(sA);
    const uint32_t sBu = (uint32_t)__cvta_generic_to_shared(sB);
    uint32_t aA[2], aB[NJJ];
#pragma unroll
    for (int i = 0; i < 2; i++)
        aA[i] = sAu + (uint32_t)(((wm * 32 + i * 16 + lr + (sel & 1) * 8) * P
                                  + (sel >> 1) * 8) * 2);
#pragma unroll
    for (int jj = 0; jj < NJJ; jj++)
        aB[jj] = sBu + (uint32_t)(((wn * (BN / 2) + jj * 16 + lr + (sel >> 1) * 8) * P
                                   + (sel & 1) * 8) * 2);

    const int r0 = tid >> 2;              // 0..63
    const int c0 = (tid & 3) * 8;         // halves
    const __half* Ap = A + (size_t)r0 * lda + c0;
    const __half* Bp = B + (size_t)r0 * ldb + c0;

    float4 ra[2], rb[BPASS];
    ra[0] = *(const float4*)Ap;
    ra[1] = *(const float4*)(Ap + (size_t)64 * lda);
#pragma unroll
    for (int p = 0; p < BPASS; p++) rb[p] = *(const float4*)(Bp + (size_t)(p * 64) * ldb);
    // store chunk 0 -> buffer 0
    *(float4*)&sA[(r0     ) * P + c0] = ra[0];
    *(float4*)&sA[(r0 + 64) * P + c0] = ra[1];
#pragma unroll
    for (int p = 0; p < BPASS; p++)
        *(float4*)&sB[(r0 + p * 64) * P + c0] = rb[p];

    const int nch = K / 32;
    for (int c = 0; c < nch; c++) {
        const int p = c & 1;
        if (c + 1 < nch) {                 // prefetch chunk c+1 into registers
            const __half* An = Ap + (c + 1) * 32;
            const __half* Bn = Bp + (c + 1) * 32;
            ra[0] = *(const float4*)An;
            ra[1] = *(const float4*)(An + (size_t)64 * lda);
#pragma unroll
            for (int pp = 0; pp < BPASS; pp++)
                rb[pp] = *(const float4*)(Bn + (size_t)(pp * 64) * ldb);
        }
        __syncthreads();                   // buffer p ready for everyone

#pragma unroll
        for (int kb = 0; kb < 2; kb++) {
            uint32_t af[2][4];
            ldsm4(af[0], aA[0] + p * (ABUFH * 2) + kb * 32);
            ldsm4(af[1], aA[1] + p * (ABUFH * 2) + kb * 32);
            uint32_t bf[NJJ][4];
#pragma unroll
            for (int jj = 0; jj < NJJ; jj++)
                ldsm4(bf[jj], aB[jj] + p * (BBUFH * 2) + kb * 32);
#pragma unroll
            for (int j = 0; j < NT; j++) {
                const uint32_t* bp = bf[j >> 1];
                const int o = (j & 1) * 2;
                mma16(acc[0][j], af[0], bp[o], bp[o + 1]);
                mma16(acc[1][j], af[1], bp[o], bp[o + 1]);
            }
        }
        if (c + 1 < nch) {                 // store chunk c+1 -> other buffer
            __half* dA = sA + (p ^ 1) * ABUFH;
            __half* dB = sB + (p ^ 1) * BBUFH;
            *(float4*)&dA[(r0     ) * P + c0] = ra[0];
            *(float4*)&dA[(r0 + 64) * P + c0] = ra[1];
#pragma unroll
            for (int pp = 0; pp < BPASS; pp++)
                *(float4*)&dB[(r0 + pp * 64) * P + c0] = rb[pp];
        }
    }
    __syncthreads();                       // smem reusable by caller after this
}
// C fragment coords: row = wm*32 + i*16 + ch*8 + g ; col = wn*(BN/2) + j*8 + q*2 (+parity)

// ============================================================================
// Kernel 0: fp32 -> fp16 conversion of inputs + weights (one pass).
// Gate params (d_in 7..12) are provably unused: TOPK == E -> all-ones mask,
// so every DGL layer is a plain affine projection.
// ============================================================================
__global__ void prep_kernel(const float* __restrict__ q, const float* __restrict__ k,
                            const float* __restrict__ v, const float* __restrict__ w,
                            const float* __restrict__ ow) {
    const size_t i  = (size_t)blockIdx.x * 256 + threadIdx.x;  // float4 index
    const size_t NX = (size_t)MR * Ee / 4;
    const size_t NW = (size_t)3 * Ee * Ee / 4;
    float4 x; __half* dst;
    if (i < NX)          { x = ((const float4*)q)[i];          dst = g_xh[0] + i * 4; }
    else if (i < 2 * NX) { x = ((const float4*)k)[i - NX];     dst = g_xh[1] + (i - NX) * 4; }
    else if (i < 3 * NX) { x = ((const float4*)v)[i - 2 * NX]; dst = g_xh[2] + (i - 2 * NX) * 4; }
    else if (i < 3 * NX + NW) {
        size_t j = i - 3 * NX;      x = ((const float4*)w)[j];  dst = g_wh + j * 4;
    } else {
        size_t j = i - 3 * NX - NW; x = ((const float4*)ow)[j]; dst = g_owh + j * 4;
    }
    *(__half2*)(dst)     = __floats2half2_rn(x.x, x.y);
    *(__half2*)(dst + 2) = __floats2half2_rn(x.z, x.w);
}

// ============================================================================
// Kernel 1: QKV projection. grid (MR/128, Ee/128, 3), 256 thr.
// ============================================================================
__global__ void __launch_bounds__(256) qkv_kernel(const float* __restrict__ bias) {
    __shared__ __align__(16) __half sh[20480];        // 2x(128*40) A + 2x(128*40) B
    const int mat = blockIdx.z;
    const int m0 = blockIdx.x * 128, n0 = blockIdx.y * 128;
    const float* bp = bias + mat * Ee;

    float acc[2][8][4] = {};
    gemm_nt_f16<128>(g_xh[mat] + (size_t)m0 * Ee,
                     g_wh + (size_t)mat * Ee * Ee + (size_t)n0 * Ee,
                     Ee, Ee, Ee, sh, sh + 10240, acc);

    const int lane = threadIdx.x & 31, g = lane >> 2, q = lane & 3;
    const int w = threadIdx.x >> 5, wm = w & 3, wn = w >> 2;

#pragma unroll
    for (int i = 0; i < 2; i++) {
#pragma unroll
        for (int ch = 0; ch < 2; ch++) {
            const int r = m0 + wm * 32 + i * 16 + ch * 8 + g;  // = t*B + b
            const int t = r >> 1, b = r & 1;
#pragma unroll
            for (int j = 0; j < 8; j++) {
                const int o = n0 + wn * 64 + j * 8 + q * 2;
                float v0 = acc[i][j][ch * 2 + 0] + bp[o];
                float v1 = acc[i][j][ch * 2 + 1] + bp[o + 1];
                const int h = o >> 6, hd = o & 63;
                const int bh = b * Hh + h;
                if (mat == 0) {
                    *(__half2*)&g_qh[((size_t)bh * Tt + t) * HDd + hd] =
                        __floats2half2_rn(v0 * 0.125f, v1 * 0.125f);
                } else if (mat == 1) {
                    *(__half2*)&g_kh[((size_t)bh * Tt + t) * HDd + hd] =
                        __floats2half2_rn(v0, v1);
                } else {
                    g_vth[((size_t)bh * HDd + hd    ) * Tt + t] = __float2half_rn(v0);
                    g_vth[((size_t)bh * HDd + hd + 1) * Tt + t] = __float2half_rn(v1);
                }
            }
        }
    }
}

// ============================================================================
// Kernel 2: FUSED scores + exp + g_s store + rowsum + AV, per (m-tile, bh).
// Loops the 16 column tiles: scores GEMM (K=64) -> exp -> coalesced store ->
// AV GEMM consuming the just-written tile (L2-hot). Row sums accumulate in
// registers; block computes rinv itself, writes g_rinv and scaled AV -> g_aoh.
// Unnormalized exp is safe: logits are O(1). grid (16, BH), 256 thr.
// ============================================================================
__global__ void __launch_bounds__(256) fused_attn_kernel() {
    __shared__ __align__(16) __half sh[20480];        // gemm bufs / 128x136 staging
    __shared__ float srow[128][2];
    const int bh = blockIdx.y, m0 = blockIdx.x * 128;
    const __half* Qg = g_qh + (size_t)bh * Tt * HDd + (size_t)m0 * HDd;
    const __half* Kg = g_kh + (size_t)bh * Tt * HDd;
    const __half* Vt = g_vth + (size_t)bh * HDd * Tt;
    __half* Srow = g_sh + ((size_t)bh * Tt + m0) * Tt;

    const int tid = threadIdx.x;
    const int lane = tid & 31, g = lane >> 2, q = lane & 3;
    const int w = tid >> 5, wm = w & 3, wn = w >> 2;
    constexpr int PS = 136;

    float accv[2][4][4] = {};
    float rsum[2][2] = {};

    for (int ntile = 0; ntile < Tt / 128; ntile++) {
        const int n0 = ntile * 128;
        float acc[2][8][4] = {};
        gemm_nt_f16<128>(Qg, Kg + (size_t)n0 * HDd, HDd, HDd, HDd,
                         sh, sh + 10240, acc);

        // exp into staging (aliases gemm bufs; safe after gemm's final sync)
#pragma unroll
        for (int i = 0; i < 2; i++) {
#pragma unroll
            for (int ch = 0; ch < 2; ch++) {
                const int rl = wm * 32 + i * 16 + ch * 8 + g;
                float rs = 0.f;
#pragma unroll
                for (int j = 0; j < 8; j++) {
                    float e0 = __expf(acc[i][j][ch * 2 + 0]);
                    float e1 = __expf(acc[i][j][ch * 2 + 1]);
                    rs += e0 + e1;
                    const int cl = wn * 64 + j * 8 + q * 2;
                    *(__half2*)&sh[rl * PS + cl] = __floats2half2_rn(e0, e1);
                }
                rs += __shfl_xor_sync(0xffffffffu, rs, 1);
                rs += __shfl_xor_sync(0xffffffffu, rs, 2);
                rsum[i][ch] += rs;        // per-(row, wn-half) running sum
            }
        }
        __syncthreads();

        // coalesced store: 16 threads per row emit 256B runs
        {
            const int rr = tid >> 4, cc = (tid & 15) * 8;
#pragma unroll
            for (int it = 0; it < 8; it++) {
                const int r = rr + it * 16;
                *(float4*)&Srow[(size_t)r * Tt + n0 + cc] = *(const float4*)&sh[r * PS + cc];
            }
        }
        __syncthreads();   // staging reads done before AV gemm overwrites sh
        // g_s writes visible to this block after syncthreads -> L2-hot A reads

        gemm_nt_f16<64>(Srow + n0, Vt + n0, Tt, Tt, 128, sh, sh + 10240, accv);
    }

    // finalize row sums -> rinv
    if (q == 0) {
#pragma unroll
        for (int i = 0; i < 2; i++)
#pragma unroll
            for (int ch = 0; ch < 2; ch++)
                srow[wm * 32 + i * 16 + ch * 8 + g][wn] = rsum[i][ch];
    }
    __syncthreads();

    const int b = bh >> 4, h = bh & 15;
#pragma unroll
    for (int i = 0; i < 2; i++) {
#pragma unroll
        for (int ch = 0; ch < 2; ch++) {
            const int rl = wm * 32 + i * 16 + ch * 8 + g;
            const float inv = 1.0f / (srow[rl][0] + srow[rl][1]);
            if (wn == 0 && q == 0)
                g_rinv[(size_t)bh * Tt + m0 + rl] = inv;
            const int t = m0 + rl;
#pragma unroll
            for (int j = 0; j < 4; j++) {
                const int col = wn * 32 + j * 8 + q * 2;
                *(__half2*)&g_aoh[((size_t)t * Bb + b) * Ee + h * HDd + col] =
                    __floats2half2_rn(accv[i][j][ch * 2 + 0] * inv,
                                      accv[i][j][ch * 2 + 1] * inv);
            }
        }
    }
}

// ============================================================================
// Kernel 3: attn_weights[b,t,s] = (1/H) sum_h expS[bh,t,s] * rinv[bh,t].
// ============================================================================
__global__ void headmean_kernel(float* __restrict__ attnw) {
    const int bt = blockIdx.x, b = bt >> 11, t = bt & (Tt - 1);
    const int c = threadIdx.x;                 // 0..511, 4 halves each
    float4 s = make_float4(0.f, 0.f, 0.f, 0.f);
#pragma unroll
    for (int h = 0; h < Hh; h++) {
        const int bh = b * Hh + h;
        const float iv = g_rinv[(size_t)bh * Tt + t];
        const uint2 raw = ((const uint2*)(g_sh + ((size_t)bh * Tt + t) * Tt))[c];
        const float2 f0 = __half22float2(*(const __half2*)&raw.x);
        const float2 f1 = __half22float2(*(const __half2*)&raw.y);
        s.x += f0.x * iv; s.y += f0.y * iv; s.z += f1.x * iv; s.w += f1.y * iv;
    }
    const float m = 1.0f / (float)Hh;
    s.x *= m; s.y *= m; s.z *= m; s.w *= m;
    ((float4*)(attnw + (size_t)bt * Tt))[c] = s;
}

// ============================================================================
// Kernel 4: out projection -> d_out (fp32). grid (MR/128, Ee/128), 256 thr.
// ============================================================================
__global__ void __launch_bounds__(256) outproj_kernel(const float* __restrict__ ob,
                                                      float* __restrict__ out) {
    __shared__ __align__(16) __half sh[20480];
    const int m0 = blockIdx.x * 128, n0 = blockIdx.y * 128;
    float acc[2][8][4] = {};
    gemm_nt_f16<128>(g_aoh + (size_t)m0 * Ee, g_owh + (size_t)n0 * Ee,
                     Ee, Ee, Ee, sh, sh + 10240, acc);

    const int lane = threadIdx.x & 31, g = lane >> 2, q = lane & 3;
    const int w = threadIdx.x >> 5, wm = w & 3, wn = w >> 2;

#pragma unroll
    for (int i = 0; i < 2; i++) {
#pragma unroll
        for (int ch = 0; ch < 2; ch++) {
            const int r = m0 + wm * 32 + i * 16 + ch * 8 + g;
#pragma unroll
            for (int j = 0; j < 8; j++) {
                const int o = n0 + wn * 64 + j * 8 + q * 2;
                float2 p = make_float2(acc[i][j][ch * 2 + 0] + ob[o],
                                       acc[i][j][ch * 2 + 1] + ob[o + 1]);
                *(float2*)&out[(size_t)r * Ee + o] = p;
            }
        }
    }
}

// ============================================================================
extern "C" void kernel_launch(void* const* d_in, const int* in_sizes, int n_in,
                              void* d_out, int out_size) {
    const float* query = (const float*)d_in[0];
    const float* key   = (const float*)d_in[1];
    const float* value = (const float*)d_in[2];
    const float* ipw   = (const float*)d_in[3];   // (3E, E)
    const float* ipb   = (const float*)d_in[4];   // (3E,)
    const float* ow    = (const float*)d_in[5];   // (E, E)
    const float* ob    = (const float*)d_in[6];   // (E,)
    // d_in[7..12]: gate params — provably unused (TOPK == E -> all-ones mask).
    (void)in_sizes; (void)n_in; (void)out_size;

    float* out   = (float*)d_out;                     // attn_output (T,B,E)
    float* attnw = out + (size_t)Tt * Bb * Ee;        // attn_weights (B,T,T)

    prep_kernel      <<<16384, 256>>>(query, key, value, ipw, ow);
    qkv_kernel       <<<dim3(MR / 128, Ee / 128, 3), 256>>>(ipb);
    fused_attn_kernel<<<dim3(Tt / 128, BH), 256>>>();
    headmean_kernel  <<<Bb * Tt, 512>>>(attnw);
    outproj_kernel   <<<dim3(MR / 128, Ee / 128), 256>>>(ob, out);
}

// round 12
// speedup vs baseline: 1.2327x; 1.2327x over previous
#include <cuda_runtime.h>
#include <cuda_fp16.h>
#include <math.h>
#include <stdint.h>

// Problem constants
#define Tt  2048
#define Bb  2
#define Ee  1024
#define Hh  16
#define HDd 64
#define BH  32          // Bb*Hh
#define MR  4096        // Tt*Bb rows

// -------- device scratch (allocation-free: static device globals) ----------
__device__ __align__(16) __half g_xh[3][(size_t)MR * Ee];    // 24 MB fp16 q/k/v inputs
__device__ __align__(16) __half g_wh[(size_t)3 * Ee * Ee];   //  6 MB fp16 in_proj_w
__device__ __align__(16) __half g_owh[(size_t)Ee * Ee];      //  2 MB fp16 out_w
__device__ __align__(16) __half g_qh[(size_t)BH * Tt * HDd]; //  8 MB (bh,t,hd), q*0.125
__device__ __align__(16) __half g_kh[(size_t)BH * Tt * HDd]; //  8 MB
__device__ __align__(16) __half g_vth[(size_t)BH * HDd * Tt];//  8 MB (bh,hd,t)
__device__ __align__(16) __half g_sh[(size_t)BH * Tt * Tt];  // 256 MB unnormalized exp(scores)
__device__ __align__(16) __half g_aoh[(size_t)MR * Ee];      //  8 MB rows = t*B+b
__device__ __align__(16) float  g_part[(size_t)BH * Tt * 32];//  8 MB rowsum partials
__device__            float  g_rinv[(size_t)BH * Tt];        // 1/rowsum

// ============================================================================
// fp16 mma m16n8k16 + ldmatrix helpers
// ============================================================================
__device__ __forceinline__ void mma16(float c[4], const uint32_t a[4],
                                      uint32_t b0, uint32_t b1) {
    asm volatile(
        "mma.sync.aligned.m16n8k16.row.col.f32.f16.f16.f32 "
        "{%0,%1,%2,%3}, {%4,%5,%6,%7}, {%8,%9}, {%0,%1,%2,%3};"
        : "+f"(c[0]), "+f"(c[1]), "+f"(c[2]), "+f"(c[3])
        : "r"(a[0]), "r"(a[1]), "r"(a[2]), "r"(a[3]), "r"(b0), "r"(b1));
}
__device__ __forceinline__ void ldsm4(uint32_t r[4], uint32_t addr) {
    asm volatile("ldmatrix.sync.aligned.m8n8.x4.shared.b16 {%0,%1,%2,%3}, [%4];"
        : "=r"(r[0]), "=r"(r[1]), "=r"(r[2]), "=r"(r[3]) : "r"(addr));
}

// ============================================================================
// NT fp16 tensor-core GEMM core, ping-pong smem (ONE __syncthreads per chunk).
//   C[m,n] += sum_k A[m,k] * B[n,k]   (both K-contiguous row-major, fp16)
// Block 256 thr (8 warps, 4x2). Block tile 128 x BN (64|128). Warp 32 x BN/2.
// K chunked by 32 halves. sA: 2 buffers of 128*40 halves; sB: 2 of BN*40.
// ============================================================================
template<int BN>
__device__ __forceinline__ void gemm_nt_f16(
    const __half* __restrict__ A, const __half* __restrict__ B,
    int lda, int ldb, int K, __half* sA, __half* sB,
    float acc[2][BN / 16][4])
{
    constexpr int NT    = BN / 16;
    constexpr int NJJ   = BN / 32;
    constexpr int P     = 40;
    constexpr int BPASS = BN / 64;
    constexpr int ABUFH = 128 * P;
    constexpr int BBUFH = BN * P;

    const int tid = threadIdx.x, lane = tid & 31;
    const int w = tid >> 5, wm = w & 3, wn = w >> 2;
    const int lr = lane & 7, sel = lane >> 3;

    const uint32_t sAu = (uint32_t)__cvta_generic_to_shared(sA);
    const uint32_t sBu = (uint32_t)__cvta_generic_to_shared(sB);
    uint32_t aA[2], aB[NJJ];
#pragma unroll
    for (int i = 0; i < 2; i++)
        aA[i] = sAu + (uint32_t)(((wm * 32 + i * 16 + lr + (sel & 1) * 8) * P
                                  + (sel >> 1) * 8) * 2);
#pragma unroll
    for (int jj = 0; jj < NJJ; jj++)
        aB[jj] = sBu + (uint32_t)(((wn * (BN / 2) + jj * 16 + lr + (sel >> 1) * 8) * P
                                   + (sel & 1) * 8) * 2);

    const int r0 = tid >> 2;              // 0..63
    const int c0 = (tid & 3) * 8;         // halves (16B groups)
    const __half* Ap = A + (size_t)r0 * lda + c0;
    const __half* Bp = B + (size_t)r0 * ldb + c0;

    float4 ra[2], rb[BPASS];
    ra[0] = *(const float4*)Ap;
    ra[1] = *(const float4*)(Ap + (size_t)64 * lda);
#pragma unroll
    for (int p = 0; p < BPASS; p++) rb[p] = *(const float4*)(Bp + (size_t)(p * 64) * ldb);
    // store chunk 0 -> buffer 0
    *(float4*)&sA[(r0     ) * P + c0] = ra[0];
    *(float4*)&sA[(r0 + 64) * P + c0] = ra[1];
#pragma unroll
    for (int p = 0; p < BPASS; p++)
        *(float4*)&sB[(r0 + p * 64) * P + c0] = rb[p];

    const int nch = K / 32;
    for (int c = 0; c < nch; c++) {
        const int p = c & 1;
        if (c + 1 < nch) {                 // prefetch chunk c+1 into registers
            const __half* An = Ap + (c + 1) * 32;
            const __half* Bn = Bp + (c + 1) * 32;
            ra[0] = *(const float4*)An;
            ra[1] = *(const float4*)(An + (size_t)64 * lda);
#pragma unroll
            for (int pp = 0; pp < BPASS; pp++)
                rb[pp] = *(const float4*)(Bn + (size_t)(pp * 64) * ldb);
        }
        __syncthreads();                   // buffer p ready for everyone

#pragma unroll
        for (int kb = 0; kb < 2; kb++) {
            uint32_t af[2][4];
            ldsm4(af[0], aA[0] + p * (ABUFH * 2) + kb * 32);
            ldsm4(af[1], aA[1] + p * (ABUFH * 2) + kb * 32);
            uint32_t bf[NJJ][4];
#pragma unroll
            for (int jj = 0; jj < NJJ; jj++)
                ldsm4(bf[jj], aB[jj] + p * (BBUFH * 2) + kb * 32);
#pragma unroll
            for (int j = 0; j < NT; j++) {
                const uint32_t* bp = bf[j >> 1];
                const int o = (j & 1) * 2;
                mma16(acc[0][j], af[0], bp[o], bp[o + 1]);
                mma16(acc[1][j], af[1], bp[o], bp[o + 1]);
            }
        }
        if (c + 1 < nch) {                 // store chunk c+1 -> other buffer
            __half* dA = sA + (p ^ 1) * ABUFH;
            __half* dB = sB + (p ^ 1) * BBUFH;
            *(float4*)&dA[(r0     ) * P + c0] = ra[0];
            *(float4*)&dA[(r0 + 64) * P + c0] = ra[1];
#pragma unroll
            for (int pp = 0; pp < BPASS; pp++)
                *(float4*)&dB[(r0 + pp * 64) * P + c0] = rb[pp];
        }
    }
    __syncthreads();                       // smem reusable by caller after this
}
// C fragment coords: row = wm*32 + i*16 + ch*8 + g ; col = wn*(BN/2) + j*8 + q*2 (+parity)

// ============================================================================
// Kernel 0: fp32 -> fp16 conversion of inputs + weights (one pass).
// Gate params (d_in 7..12) are provably unused: TOPK == E -> all-ones mask,
// so every DGL layer is a plain affine projection.
// ============================================================================
__global__ void prep_kernel(const float* __restrict__ q, const float* __restrict__ k,
                            const float* __restrict__ v, const float* __restrict__ w,
                            const float* __restrict__ ow) {
    const size_t i  = (size_t)blockIdx.x * 256 + threadIdx.x;  // float4 index
    const size_t NX = (size_t)MR * Ee / 4;
    const size_t NW = (size_t)3 * Ee * Ee / 4;
    float4 x; __half* dst;
    if (i < NX)          { x = ((const float4*)q)[i];          dst = g_xh[0] + i * 4; }
    else if (i < 2 * NX) { x = ((const float4*)k)[i - NX];     dst = g_xh[1] + (i - NX) * 4; }
    else if (i < 3 * NX) { x = ((const float4*)v)[i - 2 * NX]; dst = g_xh[2] + (i - 2 * NX) * 4; }
    else if (i < 3 * NX + NW) {
        size_t j = i - 3 * NX;      x = ((const float4*)w)[j];  dst = g_wh + j * 4;
    } else {
        size_t j = i - 3 * NX - NW; x = ((const float4*)ow)[j]; dst = g_owh + j * 4;
    }
    *(__half2*)(dst)     = __floats2half2_rn(x.x, x.y);
    *(__half2*)(dst + 2) = __floats2half2_rn(x.z, x.w);
}

// ============================================================================
// Kernel 1: QKV projection. grid (MR/128, Ee/128, 3), 256 thr.
// ============================================================================
__global__ void __launch_bounds__(256, 2) qkv_kernel(const float* __restrict__ bias) {
    __shared__ __align__(16) __half sh[20480];     // 2x(128*40) A + 2x(128*40) B
    const int mat = blockIdx.z;
    const int m0 = blockIdx.x * 128, n0 = blockIdx.y * 128;
    const float* bp = bias + mat * Ee;

    float acc[2][8][4] = {};
    gemm_nt_f16<128>(g_xh[mat] + (size_t)m0 * Ee,
                     g_wh + (size_t)mat * Ee * Ee + (size_t)n0 * Ee,
                     Ee, Ee, Ee, sh, sh + 10240, acc);

    const int lane = threadIdx.x & 31, g = lane >> 2, q = lane & 3;
    const int w = threadIdx.x >> 5, wm = w & 3, wn = w >> 2;

#pragma unroll
    for (int i = 0; i < 2; i++) {
#pragma unroll
        for (int ch = 0; ch < 2; ch++) {
            const int r = m0 + wm * 32 + i * 16 + ch * 8 + g;  // = t*B + b
            const int t = r >> 1, b = r & 1;
#pragma unroll
            for (int j = 0; j < 8; j++) {
                const int o = n0 + wn * 64 + j * 8 + q * 2;
                float v0 = acc[i][j][ch * 2 + 0] + bp[o];
                float v1 = acc[i][j][ch * 2 + 1] + bp[o + 1];
                const int h = o >> 6, hd = o & 63;
                const int bh = b * Hh + h;
                if (mat == 0) {
                    *(__half2*)&g_qh[((size_t)bh * Tt + t) * HDd + hd] =
                        __floats2half2_rn(v0 * 0.125f, v1 * 0.125f);
                } else if (mat == 1) {
                    *(__half2*)&g_kh[((size_t)bh * Tt + t) * HDd + hd] =
                        __floats2half2_rn(v0, v1);
                } else {
                    g_vth[((size_t)bh * HDd + hd    ) * Tt + t] = __float2half_rn(v0);
                    g_vth[((size_t)bh * HDd + hd + 1) * Tt + t] = __float2half_rn(v1);
                }
            }
        }
    }
}

// ============================================================================
// Kernel 2: scores + exp + rowsum partials, smem-staged coalesced store.
// Unnormalized exp is safe: logits are O(1).
// grid (16, 16, BH), 256 thr.
// ============================================================================
__global__ void __launch_bounds__(256, 2) scores_kernel() {
    __shared__ __align__(16) __half sh[20480];      // gemm bufs; reused as staging
    const int bh = blockIdx.z;
    const int m0 = blockIdx.x * 128, n0 = blockIdx.y * 128;

    float acc[2][8][4] = {};
    gemm_nt_f16<128>(g_qh + (size_t)bh * Tt * HDd + (size_t)m0 * HDd,
                     g_kh + (size_t)bh * Tt * HDd + (size_t)n0 * HDd,
                     HDd, HDd, HDd, sh, sh + 10240, acc);

    const int tid = threadIdx.x;
    const int lane = tid & 31, g = lane >> 2, q = lane & 3;
    const int w = tid >> 5, wm = w & 3, wn = w >> 2;
    constexpr int PS = 136;                          // staging pitch (16B-aligned)

#pragma unroll
    for (int i = 0; i < 2; i++) {
#pragma unroll
        for (int ch = 0; ch < 2; ch++) {
            const int rl = wm * 32 + i * 16 + ch * 8 + g;
            float rs = 0.f;
#pragma unroll
            for (int j = 0; j < 8; j++) {
                float e0 = __expf(acc[i][j][ch * 2 + 0]);
                float e1 = __expf(acc[i][j][ch * 2 + 1]);
                rs += e0 + e1;
                const int cl = wn * 64 + j * 8 + q * 2;
                *(__half2*)&sh[rl * PS + cl] = __floats2half2_rn(e0, e1);
            }
            rs += __shfl_xor_sync(0xffffffffu, rs, 1);
            rs += __shfl_xor_sync(0xffffffffu, rs, 2);
            if (q == 0)
                g_part[((size_t)bh * Tt + m0 + rl) * 32 + blockIdx.y * 2 + wn] = rs;
        }
    }
    __syncthreads();

    // coalesced store: 16 threads per row emit 256B runs
    __half* S = g_sh + ((size_t)bh * Tt + m0) * Tt + n0;
    const int rr = tid >> 4, cc = (tid & 15) * 8;
#pragma unroll
    for (int it = 0; it < 8; it++) {
        const int r = rr + it * 16;
        *(float4*)&S[(size_t)r * Tt + cc] = *(const float4*)&sh[r * PS + cc];
    }
}

// ============================================================================
// Kernel 3: reduce 32 partials per row -> 1/rowsum.
// ============================================================================
__global__ void rinv_kernel() {
    const int r = blockIdx.x * 256 + threadIdx.x;
    const float* p = &g_part[(size_t)r * 32];
    float s = 0.f;
#pragma unroll
    for (int i = 0; i < 32; i++) s += p[i];
    g_rinv[r] = 1.0f / s;
}

// ============================================================================
// Kernel 4: attn_weights[b,t,s] = (1/H) sum_h expS[bh,t,s] * rinv[bh,t].
// ============================================================================
__global__ void headmean_kernel(float* __restrict__ attnw) {
    const int bt = blockIdx.x, b = bt >> 11, t = bt & (Tt - 1);
    const int c = threadIdx.x;                 // 0..511, 4 halves each
    float4 s = make_float4(0.f, 0.f, 0.f, 0.f);
#pragma unroll
    for (int h = 0; h < Hh; h++) {
        const int bh = b * Hh + h;
        const float iv = g_rinv[(size_t)bh * Tt + t];
        const uint2 raw = ((const uint2*)(g_sh + ((size_t)bh * Tt + t) * Tt))[c];
        const float2 f0 = __half22float2(*(const __half2*)&raw.x);
        const float2 f1 = __half22float2(*(const __half2*)&raw.y);
        s.x += f0.x * iv; s.y += f0.y * iv; s.z += f1.x * iv; s.w += f1.y * iv;
    }
    const float m = 1.0f / (float)Hh;
    s.x *= m; s.y *= m; s.z *= m; s.w *= m;
    ((float4*)(attnw + (size_t)bt * Tt))[c] = s;
}

// ============================================================================
// Kernel 5: AV. D(128x64) = expS(128xTt) . Vt(64xTt)^T, scaled by rinv.
// grid (16, 1, BH), 256 thr. Writes (t*B+b, h*64+hd) fp16 layout.
// ============================================================================
__global__ void __launch_bounds__(256, 2) av_kernel() {
    __shared__ __align__(16) __half sh[15360];      // 2x(128*40) A + 2x(64*40) B
    const int bh = blockIdx.z;
    const int m0 = blockIdx.x * 128;

    float acc[2][4][4] = {};
    gemm_nt_f16<64>(g_sh + (size_t)bh * Tt * Tt + (size_t)m0 * Tt,
                    g_vth + (size_t)bh * HDd * Tt, Tt, Tt, Tt,
                    sh, sh + 10240, acc);

    const int lane = threadIdx.x & 31, g = lane >> 2, q = lane & 3;
    const int w = threadIdx.x >> 5, wm = w & 3, wn = w >> 2;
    const int b = bh >> 4, h = bh & 15;

#pragma unroll
    for (int i = 0; i < 2; i++) {
#pragma unroll
        for (int ch = 0; ch < 2; ch++) {
            const int t = m0 + wm * 32 + i * 16 + ch * 8 + g;
            const float iv = g_rinv[(size_t)bh * Tt + t];
#pragma unroll
            for (int j = 0; j < 4; j++) {
                const int col = wn * 32 + j * 8 + q * 2;
                *(__half2*)&g_aoh[((size_t)t * Bb + b) * Ee + h * HDd + col] =
                    __floats2half2_rn(acc[i][j][ch * 2 + 0] * iv,
                                      acc[i][j][ch * 2 + 1] * iv);
            }
        }
    }
}

// ============================================================================
// Kernel 6: out projection -> d_out (fp32). grid (MR/128, Ee/128), 256 thr.
// ============================================================================
__global__ void __launch_bounds__(256, 2) outproj_kernel(const float* __restrict__ ob,
                                                         float* __restrict__ out) {
    __shared__ __align__(16) __half sh[20480];
    const int m0 = blockIdx.x * 128, n0 = blockIdx.y * 128;
    float acc[2][8][4] = {};
    gemm_nt_f16<128>(g_aoh + (size_t)m0 * Ee, g_owh + (size_t)n0 * Ee,
                     Ee, Ee, Ee, sh, sh + 10240, acc);

    const int lane = threadIdx.x & 31, g = lane >> 2, q = lane & 3;
    const int w = threadIdx.x >> 5, wm = w & 3, wn = w >> 2;

#pragma unroll
    for (int i = 0; i < 2; i++) {
#pragma unroll
        for (int ch = 0; ch < 2; ch++) {
            const int r = m0 + wm * 32 + i * 16 + ch * 8 + g;
#pragma unroll
            for (int j = 0; j < 8; j++) {
                const int o = n0 + wn * 64 + j * 8 + q * 2;
                float2 p = make_float2(acc[i][j][ch * 2 + 0] + ob[o],
                                       acc[i][j][ch * 2 + 1] + ob[o + 1]);
                *(float2*)&out[(size_t)r * Ee + o] = p;
            }
        }
    }
}

// ============================================================================
extern "C" void kernel_launch(void* const* d_in, const int* in_sizes, int n_in,
                              void* d_out, int out_size) {
    const float* query = (const float*)d_in[0];
    const float* key   = (const float*)d_in[1];
    const float* value = (const float*)d_in[2];
    const float* ipw   = (const float*)d_in[3];   // (3E, E)
    const float* ipb   = (const float*)d_in[4];   // (3E,)
    const float* ow    = (const float*)d_in[5];   // (E, E)
    const float* ob    = (const float*)d_in[6];   // (E,)
    // d_in[7..12]: gate params — provably unused (TOPK == E -> all-ones mask).
    (void)in_sizes; (void)n_in; (void)out_size;

    float* out   = (float*)d_out;                     // attn_output (T,B,E)
    float* attnw = out + (size_t)Tt * Bb * Ee;        // attn_weights (B,T,T)

    prep_kernel    <<<16384, 256>>>(query, key, value, ipw, ow);
    qkv_kernel     <<<dim3(MR / 128, Ee / 128, 3), 256>>>(ipb);
    scores_kernel  <<<dim3(Tt / 128, Tt / 128, BH), 256>>>();
    rinv_kernel    <<<(BH * Tt) / 256, 256>>>();
    headmean_kernel<<<Bb * Tt, 512>>>(attnw);
    av_kernel      <<<dim3(Tt / 128, 1, BH), 256>>>();
    outproj_kernel <<<dim3(MR / 128, Ee / 128), 256>>>(ob, out);
}

// round 13
// speedup vs baseline: 1.2879x; 1.0448x over previous
#include <cuda_runtime.h>
#include <cuda_fp16.h>
#include <math.h>
#include <stdint.h>

// Problem constants
#define Tt  2048
#define Bb  2
#define Ee  1024
#define Hh  16
#define HDd 64
#define BH  32          // Bb*Hh
#define MR  4096        // Tt*Bb rows

// -------- device scratch (allocation-free: static device globals) ----------
__device__ __align__(16) __half g_xh[3][(size_t)MR * Ee];    // 24 MB fp16 q/k/v inputs
__device__ __align__(16) __half g_wh[(size_t)3 * Ee * Ee];   //  6 MB fp16 in_proj_w
__device__ __align__(16) __half g_owh[(size_t)Ee * Ee];      //  2 MB fp16 out_w
__device__ __align__(16) __half g_qh[(size_t)BH * Tt * HDd]; //  8 MB (bh,t,hd), q*0.125
__device__ __align__(16) __half g_kh[(size_t)BH * Tt * HDd]; //  8 MB
__device__ __align__(16) __half g_vth[(size_t)BH * HDd * Tt];//  8 MB (bh,hd,t)
__device__ __align__(16) __half g_sh[(size_t)BH * Tt * Tt];  // 256 MB unnormalized exp(scores)
__device__ __align__(16) __half g_aoh[(size_t)MR * Ee];      //  8 MB rows = t*B+b
__device__ __align__(16) float  g_part[(size_t)BH * Tt * 32];//  8 MB rowsum partials
__device__            float  g_rinv[(size_t)BH * Tt];        // 1/rowsum

// ============================================================================
// fp16 mma m16n8k16 + ldmatrix + cp.async helpers
// ============================================================================
__device__ __forceinline__ void mma16(float c[4], const uint32_t a[4],
                                      uint32_t b0, uint32_t b1) {
    asm volatile(
        "mma.sync.aligned.m16n8k16.row.col.f32.f16.f16.f32 "
        "{%0,%1,%2,%3}, {%4,%5,%6,%7}, {%8,%9}, {%0,%1,%2,%3};"
        : "+f"(c[0]), "+f"(c[1]), "+f"(c[2]), "+f"(c[3])
        : "r"(a[0]), "r"(a[1]), "r"(a[2]), "r"(a[3]), "r"(b0), "r"(b1));
}
__device__ __forceinline__ void ldsm4(uint32_t r[4], uint32_t addr) {
    asm volatile("ldmatrix.sync.aligned.m8n8.x4.shared.b16 {%0,%1,%2,%3}, [%4];"
        : "=r"(r[0]), "=r"(r[1]), "=r"(r[2]), "=r"(r[3]) : "r"(addr));
}
__device__ __forceinline__ void cpa16(uint32_t dst, const void* src) {
    asm volatile("cp.async.cg.shared.global [%0], [%1], 16;" :: "r"(dst), "l"(src));
}
#define CPA_COMMIT() asm volatile("cp.async.commit_group;" ::: "memory")
#define CPA_WAIT0()  asm volatile("cp.async.wait_group 0;"  ::: "memory")

// ============================================================================
// NT fp16 tensor-core GEMM core, cp.async 2-stage pipeline.
//   C[m,n] += sum_k A[m,k] * B[n,k]   (both K-contiguous row-major, fp16)
// Block 256 thr (8 warps, 4x2). Block tile 128 x BN (64|128). Warp 32 x BN/2.
// K chunked by 32 halves. Per chunk: wait -> sync -> cp.async next -> compute.
// sA: 2 buffers of 128*40 halves; sB: 2 of BN*40. ONE sync per chunk; the
// global->smem copy runs in the async pipe underneath the mma block.
// ============================================================================
template<int BN>
__device__ __forceinline__ void gemm_nt_f16(
    const __half* __restrict__ A, const __half* __restrict__ B,
    int lda, int ldb, int K, __half* sA, __half* sB,
    float acc[2][BN / 16][4])
{
    constexpr int NT    = BN / 16;
    constexpr int NJJ   = BN / 32;
    constexpr int P     = 40;
    constexpr int BPASS = BN / 64;            // B row-passes (1 or 2)
    constexpr int ABUFB = 128 * P * 2;        // bytes per A buffer
    constexpr int BBUFB = BN * P * 2;

    const int tid = threadIdx.x, lane = tid & 31;
    const int w = tid >> 5, wm = w & 3, wn = w >> 2;
    const int lr = lane & 7, sel = lane >> 3;

    const uint32_t sAu = (uint32_t)__cvta_generic_to_shared(sA);
    const uint32_t sBu = (uint32_t)__cvta_generic_to_shared(sB);
    uint32_t aA[2], aB[NJJ];
#pragma unroll
    for (int i = 0; i < 2; i++)
        aA[i] = sAu + (uint32_t)(((wm * 32 + i * 16 + lr + (sel & 1) * 8) * P
                                  + (sel >> 1) * 8) * 2);
#pragma unroll
    for (int jj = 0; jj < NJJ; jj++)
        aB[jj] = sBu + (uint32_t)(((wn * (BN / 2) + jj * 16 + lr + (sel >> 1) * 8) * P
                                   + (sel & 1) * 8) * 2);

    const int r0 = tid >> 2;                  // 0..63
    const int c0 = (tid & 3) * 8;             // halves (16B)
    const __half* Ap = A + (size_t)r0 * lda + c0;
    const __half* Bp = B + (size_t)r0 * ldb + c0;
    const uint32_t dA0 = sAu + (uint32_t)((r0 * P + c0) * 2);
    const uint32_t dA1 = sAu + (uint32_t)(((r0 + 64) * P + c0) * 2);
    const uint32_t dB0 = sBu + (uint32_t)((r0 * P + c0) * 2);

    // stage chunk 0 -> buffer 0
    cpa16(dA0, Ap);
    cpa16(dA1, Ap + (size_t)64 * lda);
#pragma unroll
    for (int pp = 0; pp < BPASS; pp++)
        cpa16(dB0 + pp * (64 * P * 2), Bp + (size_t)(pp * 64) * ldb);
    CPA_COMMIT();

    const int nch = K / 32;
    for (int c = 0; c < nch; c++) {
        const int p = c & 1;
        CPA_WAIT0();                          // chunk c landed
        __syncthreads();                      // + all warps done with buffer p^1

        if (c + 1 < nch) {                    // stage chunk c+1 into freed buffer
            const int off = (p ^ 1) ? 1 : 0;
            const uint32_t ao = off * ABUFB, bo = off * BBUFB;
            const __half* An = Ap + (c + 1) * 32;
            const __half* Bn = Bp + (c + 1) * 32;
            cpa16(dA0 + ao, An);
            cpa16(dA1 + ao, An + (size_t)64 * lda);
#pragma unroll
            for (int pp = 0; pp < BPASS; pp++)
                cpa16(dB0 + bo + pp * (64 * P * 2), Bn + (size_t)(pp * 64) * ldb);
            CPA_COMMIT();
        }

#pragma unroll
        for (int kb = 0; kb < 2; kb++) {
            uint32_t af[2][4];
            ldsm4(af[0], aA[0] + p * ABUFB + kb * 32);
            ldsm4(af[1], aA[1] + p * ABUFB + kb * 32);
            uint32_t bf[NJJ][4];
#pragma unroll
            for (int jj = 0; jj < NJJ; jj++)
                ldsm4(bf[jj], aB[jj] + p * BBUFB + kb * 32);
#pragma unroll
            for (int j = 0; j < NT; j++) {
                const uint32_t* bp = bf[j >> 1];
                const int o = (j & 1) * 2;
                mma16(acc[0][j], af[0], bp[o], bp[o + 1]);
                mma16(acc[1][j], af[1], bp[o], bp[o + 1]);
            }
        }
    }
    __syncthreads();                          // smem reusable by caller
}
// C fragment coords: row = wm*32 + i*16 + ch*8 + g ; col = wn*(BN/2) + j*8 + q*2 (+parity)

// ============================================================================
// Kernel 0: fp32 -> fp16 conversion of inputs + weights (one pass).
// Gate params (d_in 7..12) are provably unused: TOPK == E -> all-ones mask,
// so every DGL layer is a plain affine projection.
// ============================================================================
__global__ void prep_kernel(const float* __restrict__ q, const float* __restrict__ k,
                            const float* __restrict__ v, const float* __restrict__ w,
                            const float* __restrict__ ow) {
    const size_t i  = (size_t)blockIdx.x * 256 + threadIdx.x;  // float4 index
    const size_t NX = (size_t)MR * Ee / 4;
    const size_t NW = (size_t)3 * Ee * Ee / 4;
    float4 x; __half* dst;
    if (i < NX)          { x = ((const float4*)q)[i];          dst = g_xh[0] + i * 4; }
    else if (i < 2 * NX) { x = ((const float4*)k)[i - NX];     dst = g_xh[1] + (i - NX) * 4; }
    else if (i < 3 * NX) { x = ((const float4*)v)[i - 2 * NX]; dst = g_xh[2] + (i - 2 * NX) * 4; }
    else if (i < 3 * NX + NW) {
        size_t j = i - 3 * NX;      x = ((const float4*)w)[j];  dst = g_wh + j * 4;
    } else {
        size_t j = i - 3 * NX - NW; x = ((const float4*)ow)[j]; dst = g_owh + j * 4;
    }
    *(__half2*)(dst)     = __floats2half2_rn(x.x, x.y);
    *(__half2*)(dst + 2) = __floats2half2_rn(x.z, x.w);
}

// ============================================================================
// Kernel 1: QKV projection. grid (MR/128, Ee/128, 3), 256 thr.
// ============================================================================
__global__ void __launch_bounds__(256, 2) qkv_kernel(const float* __restrict__ bias) {
    __shared__ __align__(16) __half sh[20480];     // 2x(128*40) A + 2x(128*40) B
    const int mat = blockIdx.z;
    const int m0 = blockIdx.x * 128, n0 = blockIdx.y * 128;
    const float* bp = bias + mat * Ee;

    float acc[2][8][4] = {};
    gemm_nt_f16<128>(g_xh[mat] + (size_t)m0 * Ee,
                     g_wh + (size_t)mat * Ee * Ee + (size_t)n0 * Ee,
                     Ee, Ee, Ee, sh, sh + 10240, acc);

    const int lane = threadIdx.x & 31, g = lane >> 2, q = lane & 3;
    const int w = threadIdx.x >> 5, wm = w & 3, wn = w >> 2;

#pragma unroll
    for (int i = 0; i < 2; i++) {
#pragma unroll
        for (int ch = 0; ch < 2; ch++) {
            const int r = m0 + wm * 32 + i * 16 + ch * 8 + g;  // = t*B + b
            const int t = r >> 1, b = r & 1;
#pragma unroll
            for (int j = 0; j < 8; j++) {
                const int o = n0 + wn * 64 + j * 8 + q * 2;
                float v0 = acc[i][j][ch * 2 + 0] + bp[o];
                float v1 = acc[i][j][ch * 2 + 1] + bp[o + 1];
                const int h = o >> 6, hd = o & 63;
                const int bh = b * Hh + h;
                if (mat == 0) {
                    *(__half2*)&g_qh[((size_t)bh * Tt + t) * HDd + hd] =
                        __floats2half2_rn(v0 * 0.125f, v1 * 0.125f);
                } else if (mat == 1) {
                    *(__half2*)&g_kh[((size_t)bh * Tt + t) * HDd + hd] =
                        __floats2half2_rn(v0, v1);
                } else {
                    g_vth[((size_t)bh * HDd + hd    ) * Tt + t] = __float2half_rn(v0);
                    g_vth[((size_t)bh * HDd + hd + 1) * Tt + t] = __float2half_rn(v1);
                }
            }
        }
    }
}

// ============================================================================
// Kernel 2: scores + exp + rowsum partials, smem-staged coalesced store.
// Unnormalized exp is safe: logits are O(1).
// grid (16, 16, BH), 256 thr.
// ============================================================================
__global__ void __launch_bounds__(256, 2) scores_kernel() {
    __shared__ __align__(16) __half sh[20480];      // gemm bufs; reused as staging
    const int bh = blockIdx.z;
    const int m0 = blockIdx.x * 128, n0 = blockIdx.y * 128;

    float acc[2][8][4] = {};
    gemm_nt_f16<128>(g_qh + (size_t)bh * Tt * HDd + (size_t)m0 * HDd,
                     g_kh + (size_t)bh * Tt * HDd + (size_t)n0 * HDd,
                     HDd, HDd, HDd, sh, sh + 10240, acc);

    const int tid = threadIdx.x;
    const int lane = tid & 31, g = lane >> 2, q = lane & 3;
    const int w = tid >> 5, wm = w & 3, wn = w >> 2;
    constexpr int PS = 136;                          // staging pitch (16B-aligned)

#pragma unroll
    for (int i = 0; i < 2; i++) {
#pragma unroll
        for (int ch = 0; ch < 2; ch++) {
            const int rl = wm * 32 + i * 16 + ch * 8 + g;
            float rs = 0.f;
#pragma unroll
            for (int j = 0; j < 8; j++) {
                float e0 = __expf(acc[i][j][ch * 2 + 0]);
                float e1 = __expf(acc[i][j][ch * 2 + 1]);
                rs += e0 + e1;
                const int cl = wn * 64 + j * 8 + q * 2;
                *(__half2*)&sh[rl * PS + cl] = __floats2half2_rn(e0, e1);
            }
            rs += __shfl_xor_sync(0xffffffffu, rs, 1);
            rs += __shfl_xor_sync(0xffffffffu, rs, 2);
            if (q == 0)
                g_part[((size_t)bh * Tt + m0 + rl) * 32 + blockIdx.y * 2 + wn] = rs;
        }
    }
    __syncthreads();

    // coalesced store: 16 threads per row emit 256B runs
    __half* S = g_sh + ((size_t)bh * Tt + m0) * Tt + n0;
    const int rr = tid >> 4, cc = (tid & 15) * 8;
#pragma unroll
    for (int it = 0; it < 8; it++) {
        const int r = rr + it * 16;
        *(float4*)&S[(size_t)r * Tt + cc] = *(const float4*)&sh[r * PS + cc];
    }
}

// ============================================================================
// Kernel 3: reduce 32 partials per row -> 1/rowsum.
// ============================================================================
__global__ void rinv_kernel() {
    const int r = blockIdx.x * 256 + threadIdx.x;
    const float* p = &g_part[(size_t)r * 32];
    float s = 0.f;
#pragma unroll
    for (int i = 0; i < 32; i++) s += p[i];
    g_rinv[r] = 1.0f / s;
}

// ============================================================================
// Kernel 4: attn_weights[b,t,s] = (1/H) sum_h expS[bh,t,s] * rinv[bh,t].
// ============================================================================
__global__ void headmean_kernel(float* __restrict__ attnw) {
    const int bt = blockIdx.x, b = bt >> 11, t = bt & (Tt - 1);
    const int c = threadIdx.x;                 // 0..511, 4 halves each
    float4 s = make_float4(0.f, 0.f, 0.f, 0.f);
#pragma unroll
    for (int h = 0; h < Hh; h++) {
        const int bh = b * Hh + h;
        const float iv = g_rinv[(size_t)bh * Tt + t];
        const uint2 raw = ((const uint2*)(g_sh + ((size_t)bh * Tt + t) * Tt))[c];
        const float2 f0 = __half22float2(*(const __half2*)&raw.x);
        const float2 f1 = __half22float2(*(const __half2*)&raw.y);
        s.x += f0.x * iv; s.y += f0.y * iv; s.z += f1.x * iv; s.w += f1.y * iv;
    }
    const float m = 1.0f / (float)Hh;
    s.x *= m; s.y *= m; s.z *= m; s.w *= m;
    ((float4*)(attnw + (size_t)bt * Tt))[c] = s;
}

// ============================================================================
// Kernel 5: AV. D(128x64) = expS(128xTt) . Vt(64xTt)^T, scaled by rinv.
// grid (16, 1, BH), 256 thr. Writes (t*B+b, h*64+hd) fp16 layout.
// ============================================================================
__global__ void __launch_bounds__(256, 2) av_kernel() {
    __shared__ __align__(16) __half sh[15360];      // 2x(128*40) A + 2x(64*40) B
    const int bh = blockIdx.z;
    const int m0 = blockIdx.x * 128;

    float acc[2][4][4] = {};
    gemm_nt_f16<64>(g_sh + (size_t)bh * Tt * Tt + (size_t)m0 * Tt,
                    g_vth + (size_t)bh * HDd * Tt, Tt, Tt, Tt,
                    sh, sh + 10240, acc);

    const int lane = threadIdx.x & 31, g = lane >> 2, q = lane & 3;
    const int w = threadIdx.x >> 5, wm = w & 3, wn = w >> 2;
    const int b = bh >> 4, h = bh & 15;

#pragma unroll
    for (int i = 0; i < 2; i++) {
#pragma unroll
        for (int ch = 0; ch < 2; ch++) {
            const int t = m0 + wm * 32 + i * 16 + ch * 8 + g;
            const float iv = g_rinv[(size_t)bh * Tt + t];
#pragma unroll
            for (int j = 0; j < 4; j++) {
                const int col = wn * 32 + j * 8 + q * 2;
                *(__half2*)&g_aoh[((size_t)t * Bb + b) * Ee + h * HDd + col] =
                    __floats2half2_rn(acc[i][j][ch * 2 + 0] * iv,
                                      acc[i][j][ch * 2 + 1] * iv);
            }
        }
    }
}

// ============================================================================
// Kernel 6: out projection -> d_out (fp32). grid (MR/128, Ee/128), 256 thr.
// ============================================================================
__global__ void __launch_bounds__(256, 2) outproj_kernel(const float* __restrict__ ob,
                                                         float* __restrict__ out) {
    __shared__ __align__(16) __half sh[20480];
    const int m0 = blockIdx.x * 128, n0 = blockIdx.y * 128;
    float acc[2][8][4] = {};
    gemm_nt_f16<128>(g_aoh + (size_t)m0 * Ee, g_owh + (size_t)n0 * Ee,
                     Ee, Ee, Ee, sh, sh + 10240, acc);

    const int lane = threadIdx.x & 31, g = lane >> 2, q = lane & 3;
    const int w = threadIdx.x >> 5, wm = w & 3, wn = w >> 2;

#pragma unroll
    for (int i = 0; i < 2; i++) {
#pragma unroll
        for (int ch = 0; ch < 2; ch++) {
            const int r = m0 + wm * 32 + i * 16 + ch * 8 + g;
#pragma unroll
            for (int j = 0; j < 8; j++) {
                const int o = n0 + wn * 64 + j * 8 + q * 2;
                float2 p = make_float2(acc[i][j][ch * 2 + 0] + ob[o],
                                       acc[i][j][ch * 2 + 1] + ob[o + 1]);
                *(float2*)&out[(size_t)r * Ee + o] = p;
            }
        }
    }
}

// ============================================================================
extern "C" void kernel_launch(void* const* d_in, const int* in_sizes, int n_in,
                              void* d_out, int out_size) {
    const float* query = (const float*)d_in[0];
    const float* key   = (const float*)d_in[1];
    const float* value = (const float*)d_in[2];
    const float* ipw   = (const float*)d_in[3];   // (3E, E)
    const float* ipb   = (const float*)d_in[4];   // (3E,)
    const float* ow    = (const float*)d_in[5];   // (E, E)
    const float* ob    = (const float*)d_in[6];   // (E,)
    // d_in[7..12]: gate params — provably unused (TOPK == E -> all-ones mask).
    (void)in_sizes; (void)n_in; (void)out_size;

    float* out   = (float*)d_out;                     // attn_output (T,B,E)
    float* attnw = out + (size_t)Tt * Bb * Ee;        // attn_weights (B,T,T)

    prep_kernel    <<<16384, 256>>>(query, key, value, ipw, ow);
    qkv_kernel     <<<dim3(MR / 128, Ee / 128, 3), 256>>>(ipb);
    scores_kernel  <<<dim3(Tt / 128, Tt / 128, BH), 256>>>();
    rinv_kernel    <<<(BH * Tt) / 256, 256>>>();
    headmean_kernel<<<Bb * Tt, 512>>>(attnw);
    av_kernel      <<<dim3(Tt / 128, 1, BH), 256>>>();
    outproj_kernel <<<dim3(MR / 128, Ee / 128), 256>>>(ob, out);
}

// round 14
// speedup vs baseline: 1.3767x; 1.0690x over previous
#include <cuda_runtime.h>
#include <cuda_fp16.h>
#include <math.h>
#include <stdint.h>

// Problem constants
#define Tt  2048
#define Bb  2
#define Ee  1024
#define Hh  16
#define HDd 64
#define BH  32          // Bb*Hh
#define MR  4096        // Tt*Bb rows

// -------- device scratch (allocation-free: static device globals) ----------
__device__ __align__(16) __half g_xh[3][(size_t)MR * Ee];    // 24 MB fp16 q/k/v inputs
__device__ __align__(16) __half g_wh[(size_t)3 * Ee * Ee];   //  6 MB fp16 in_proj_w
__device__ __align__(16) __half g_owh[(size_t)Ee * Ee];      //  2 MB fp16 out_w
__device__ __align__(16) __half g_qh[(size_t)BH * Tt * HDd]; //  8 MB (bh,t,hd), q*0.125
__device__ __align__(16) __half g_kh[(size_t)BH * Tt * HDd]; //  8 MB
__device__ __align__(16) __half g_vth[(size_t)BH * HDd * Tt];//  8 MB (bh,hd,t)
__device__ __align__(16) __half g_sh[(size_t)BH * Tt * Tt];  // 256 MB unnormalized exp(scores)
__device__ __align__(16) __half g_aoh[(size_t)MR * Ee];      //  8 MB rows = t*B+b
__device__ __align__(16) float  g_part[(size_t)BH * Tt * 32];//  8 MB rowsum partials

// ============================================================================
// fp16 mma m16n8k16 + ldmatrix + cp.async helpers
// ============================================================================
__device__ __forceinline__ void mma16(float c[4], const uint32_t a[4],
                                      uint32_t b0, uint32_t b1) {
    asm volatile(
        "mma.sync.aligned.m16n8k16.row.col.f32.f16.f16.f32 "
        "{%0,%1,%2,%3}, {%4,%5,%6,%7}, {%8,%9}, {%0,%1,%2,%3};"
        : "+f"(c[0]), "+f"(c[1]), "+f"(c[2]), "+f"(c[3])
        : "r"(a[0]), "r"(a[1]), "r"(a[2]), "r"(a[3]), "r"(b0), "r"(b1));
}
__device__ __forceinline__ void ldsm4(uint32_t r[4], uint32_t addr) {
    asm volatile("ldmatrix.sync.aligned.m8n8.x4.shared.b16 {%0,%1,%2,%3}, [%4];"
        : "=r"(r[0]), "=r"(r[1]), "=r"(r[2]), "=r"(r[3]) : "r"(addr));
}
__device__ __forceinline__ void cpa16(uint32_t dst, const void* src) {
    asm volatile("cp.async.cg.shared.global [%0], [%1], 16;" :: "r"(dst), "l"(src));
}
#define CPA_COMMIT() asm volatile("cp.async.commit_group;" ::: "memory")
#define CPA_WAIT0()  asm volatile("cp.async.wait_group 0;"  ::: "memory")

// ============================================================================
// NT fp16 tensor-core GEMM core, cp.async 2-stage pipeline, K-chunk = 64.
//   C[m,n] += sum_k A[m,k] * B[n,k]   (both K-contiguous row-major, fp16)
// Block 256 thr (8 warps, 4x2). Block tile 128 x BN (64|128). Warp 32 x BN/2.
// Pitch P=72 halves (144B rows = +4 banks/row): ldmatrix 8-row fetches span
// all 32 banks. One __syncthreads per 64-K chunk.
// sA: 2 buffers of 128*72 halves; sB: 2 of BN*72. Dynamic smem.
// ============================================================================
template<int BN>
__device__ __forceinline__ void gemm_nt_f16(
    const __half* __restrict__ A, const __half* __restrict__ B,
    int lda, int ldb, int K, __half* sA, __half* sB,
    float acc[2][BN / 16][4])
{
    constexpr int NT    = BN / 16;
    constexpr int NJJ   = BN / 32;
    constexpr int P     = 72;
    constexpr int ABUFB = 128 * P * 2;        // bytes per A buffer (18432)
    constexpr int BBUFB = BN * P * 2;

    const int tid = threadIdx.x, lane = tid & 31;
    const int w = tid >> 5, wm = w & 3, wn = w >> 2;
    const int lr = lane & 7, sel = lane >> 3;

    const uint32_t sAu = (uint32_t)__cvta_generic_to_shared(sA);
    const uint32_t sBu = (uint32_t)__cvta_generic_to_shared(sB);
    uint32_t aA[2], aB[NJJ];
#pragma unroll
    for (int i = 0; i < 2; i++)
        aA[i] = sAu + (uint32_t)(((wm * 32 + i * 16 + lr + (sel & 1) * 8) * P
                                  + (sel >> 1) * 8) * 2);
#pragma unroll
    for (int jj = 0; jj < NJJ; jj++)
        aB[jj] = sBu + (uint32_t)(((wn * (BN / 2) + jj * 16 + lr + (sel >> 1) * 8) * P
                                   + (sel & 1) * 8) * 2);

    // cp.async mapping: 256 threads cover 32 rows x 64 halves per pass
    const int rA = tid >> 3;                  // 0..31
    const int cA = (tid & 7) * 8;             // halves (16B groups)
    const uint32_t dA = sAu + (uint32_t)((rA * P + cA) * 2);
    const uint32_t dB = sBu + (uint32_t)((rA * P + cA) * 2);
    const __half* Ag = A + (size_t)rA * lda + cA;
    const __half* Bg = B + (size_t)rA * ldb + cA;

#define STAGE_CHUNK(cc, buf) do {                                              \
    const uint32_t _ao = (buf) * ABUFB, _bo = (buf) * BBUFB;                   \
    const __half* _As = Ag + (cc) * 64;                                        \
    const __half* _Bs = Bg + (cc) * 64;                                        \
    _Pragma("unroll")                                                          \
    for (int ii = 0; ii < 4; ii++)                                             \
        cpa16(dA + _ao + ii * (32 * P * 2), _As + (size_t)(ii * 32) * lda);    \
    _Pragma("unroll")                                                          \
    for (int ii = 0; ii < BN / 32; ii++)                                       \
        cpa16(dB + _bo + ii * (32 * P * 2), _Bs + (size_t)(ii * 32) * ldb);    \
    CPA_COMMIT();                                                              \
} while (0)

    STAGE_CHUNK(0, 0);

    const int nch = K / 64;
    for (int c = 0; c < nch; c++) {
        const int p = c & 1;
        CPA_WAIT0();                          // chunk c landed
        __syncthreads();                      // + all warps done with buffer p^1

        if (c + 1 < nch) STAGE_CHUNK(c + 1, p ^ 1);

#pragma unroll
        for (int kb = 0; kb < 4; kb++) {      // four k16 steps per 64-chunk
            uint32_t af[2][4];
            ldsm4(af[0], aA[0] + p * ABUFB + kb * 32);
            ldsm4(af[1], aA[1] + p * ABUFB + kb * 32);
            uint32_t bf[NJJ][4];
#pragma unroll
            for (int jj = 0; jj < NJJ; jj++)
                ldsm4(bf[jj], aB[jj] + p * BBUFB + kb * 32);
#pragma unroll
            for (int j = 0; j < NT; j++) {
                const uint32_t* bp = bf[j >> 1];
                const int o = (j & 1) * 2;
                mma16(acc[0][j], af[0], bp[o], bp[o + 1]);
                mma16(acc[1][j], af[1], bp[o], bp[o + 1]);
            }
        }
    }
    __syncthreads();                          // smem reusable by caller
#undef STAGE_CHUNK
}
// C fragment coords: row = wm*32 + i*16 + ch*8 + g ; col = wn*(BN/2) + j*8 + q*2 (+parity)

#define SMEM_BN128 (2 * (128 * 72 + 128 * 72) * 2)   // 73728 B
#define SMEM_BN64  (2 * (128 * 72 + 64 * 72) * 2)    // 55296 B

// ============================================================================
// Kernel 0: fp32 -> fp16 conversion of inputs + weights (one pass).
// Gate params (d_in 7..12) are provably unused: TOPK == E -> all-ones mask,
// so every DGL layer is a plain affine projection.
// ============================================================================
__global__ void prep_kernel(const float* __restrict__ q, const float* __restrict__ k,
                            const float* __restrict__ v, const float* __restrict__ w,
                            const float* __restrict__ ow) {
    const size_t i  = (size_t)blockIdx.x * 256 + threadIdx.x;  // float4 index
    const size_t NX = (size_t)MR * Ee / 4;
    const size_t NW = (size_t)3 * Ee * Ee / 4;
    float4 x; __half* dst;
    if (i < NX)          { x = ((const float4*)q)[i];          dst = g_xh[0] + i * 4; }
    else if (i < 2 * NX) { x = ((const float4*)k)[i - NX];     dst = g_xh[1] + (i - NX) * 4; }
    else if (i < 3 * NX) { x = ((const float4*)v)[i - 2 * NX]; dst = g_xh[2] + (i - 2 * NX) * 4; }
    else if (i < 3 * NX + NW) {
        size_t j = i - 3 * NX;      x = ((const float4*)w)[j];  dst = g_wh + j * 4;
    } else {
        size_t j = i - 3 * NX - NW; x = ((const float4*)ow)[j]; dst = g_owh + j * 4;
    }
    *(__half2*)(dst)     = __floats2half2_rn(x.x, x.y);
    *(__half2*)(dst + 2) = __floats2half2_rn(x.z, x.w);
}

// ============================================================================
// Kernel 1: QKV projection. grid (MR/128, Ee/128, 3), 256 thr.
// ============================================================================
__global__ void __launch_bounds__(256, 2) qkv_kernel(const float* __restrict__ bias) {
    extern __shared__ __half sh[];
    const int mat = blockIdx.z;
    const int m0 = blockIdx.x * 128, n0 = blockIdx.y * 128;
    const float* bp = bias + mat * Ee;

    float acc[2][8][4] = {};
    gemm_nt_f16<128>(g_xh[mat] + (size_t)m0 * Ee,
                     g_wh + (size_t)mat * Ee * Ee + (size_t)n0 * Ee,
                     Ee, Ee, Ee, sh, sh + 2 * 128 * 72, acc);

    const int lane = threadIdx.x & 31, g = lane >> 2, q = lane & 3;
    const int w = threadIdx.x >> 5, wm = w & 3, wn = w >> 2;

#pragma unroll
    for (int i = 0; i < 2; i++) {
#pragma unroll
        for (int ch = 0; ch < 2; ch++) {
            const int r = m0 + wm * 32 + i * 16 + ch * 8 + g;  // = t*B + b
            const int t = r >> 1, b = r & 1;
#pragma unroll
            for (int j = 0; j < 8; j++) {
                const int o = n0 + wn * 64 + j * 8 + q * 2;
                float v0 = acc[i][j][ch * 2 + 0] + bp[o];
                float v1 = acc[i][j][ch * 2 + 1] + bp[o + 1];
                const int h = o >> 6, hd = o & 63;
                const int bh = b * Hh + h;
                if (mat == 0) {
                    *(__half2*)&g_qh[((size_t)bh * Tt + t) * HDd + hd] =
                        __floats2half2_rn(v0 * 0.125f, v1 * 0.125f);
                } else if (mat == 1) {
                    *(__half2*)&g_kh[((size_t)bh * Tt + t) * HDd + hd] =
                        __floats2half2_rn(v0, v1);
                } else {
                    g_vth[((size_t)bh * HDd + hd    ) * Tt + t] = __float2half_rn(v0);
                    g_vth[((size_t)bh * HDd + hd + 1) * Tt + t] = __float2half_rn(v1);
                }
            }
        }
    }
}

// ============================================================================
// Kernel 2: scores + exp + rowsum partials, smem-staged coalesced store.
// Unnormalized exp is safe: logits are O(1).
// grid (16, 16, BH), 256 thr.
// ============================================================================
__global__ void __launch_bounds__(256, 2) scores_kernel() {
    extern __shared__ __half sh[];                   // gemm bufs; reused as staging
    const int bh = blockIdx.z;
    const int m0 = blockIdx.x * 128, n0 = blockIdx.y * 128;

    float acc[2][8][4] = {};
    gemm_nt_f16<128>(g_qh + (size_t)bh * Tt * HDd + (size_t)m0 * HDd,
                     g_kh + (size_t)bh * Tt * HDd + (size_t)n0 * HDd,
                     HDd, HDd, HDd, sh, sh + 2 * 128 * 72, acc);

    const int tid = threadIdx.x;
    const int lane = tid & 31, g = lane >> 2, q = lane & 3;
    const int w = tid >> 5, wm = w & 3, wn = w >> 2;
    constexpr int PS = 136;                          // staging pitch (16B-aligned)

#pragma unroll
    for (int i = 0; i < 2; i++) {
#pragma unroll
        for (int ch = 0; ch < 2; ch++) {
            const int rl = wm * 32 + i * 16 + ch * 8 + g;
            float rs = 0.f;
#pragma unroll
            for (int j = 0; j < 8; j++) {
                float e0 = __expf(acc[i][j][ch * 2 + 0]);
                float e1 = __expf(acc[i][j][ch * 2 + 1]);
                rs += e0 + e1;
                const int cl = wn * 64 + j * 8 + q * 2;
                *(__half2*)&sh[rl * PS + cl] = __floats2half2_rn(e0, e1);
            }
            rs += __shfl_xor_sync(0xffffffffu, rs, 1);
            rs += __shfl_xor_sync(0xffffffffu, rs, 2);
            if (q == 0)
                g_part[((size_t)bh * Tt + m0 + rl) * 32 + blockIdx.y * 2 + wn] = rs;
        }
    }
    __syncthreads();

    // coalesced store: 16 threads per row emit 256B runs
    __half* S = g_sh + ((size_t)bh * Tt + m0) * Tt + n0;
    const int rr = tid >> 4, cc = (tid & 15) * 8;
#pragma unroll
    for (int it = 0; it < 8; it++) {
        const int r = rr + it * 16;
        *(float4*)&S[(size_t)r * Tt + cc] = *(const float4*)&sh[r * PS + cc];
    }
}

// ============================================================================
// Kernel 3: attn_weights[b,t,s] = (1/H) sum_h expS[bh,t,s] * rinv[bh,t].
// rinv reconstructed inline from g_part (deterministic 32-float sums).
// ============================================================================
__global__ void headmean_kernel(float* __restrict__ attnw) {
    __shared__ float siv[Hh];
    const int bt = blockIdx.x, b = bt >> 11, t = bt & (Tt - 1);
    if (threadIdx.x < Hh) {
        const float* p = &g_part[((size_t)(b * Hh + threadIdx.x) * Tt + t) * 32];
        float s = 0.f;
#pragma unroll
        for (int i = 0; i < 32; i++) s += p[i];
        siv[threadIdx.x] = 1.0f / s;
    }
    __syncthreads();

    const int c = threadIdx.x;                 // 0..511, 4 halves each
    float4 s = make_float4(0.f, 0.f, 0.f, 0.f);
#pragma unroll
    for (int h = 0; h < Hh; h++) {
        const int bh = b * Hh + h;
        const float iv = siv[h];
        const uint2 raw = ((const uint2*)(g_sh + ((size_t)bh * Tt + t) * Tt))[c];
        const float2 f0 = __half22float2(*(const __half2*)&raw.x);
        const float2 f1 = __half22float2(*(const __half2*)&raw.y);
        s.x += f0.x * iv; s.y += f0.y * iv; s.z += f1.x * iv; s.w += f1.y * iv;
    }
    const float m = 1.0f / (float)Hh;
    s.x *= m; s.y *= m; s.z *= m; s.w *= m;
    ((float4*)(attnw + (size_t)bt * Tt))[c] = s;
}

// ============================================================================
// Kernel 4: AV. D(128x64) = expS(128xTt) . Vt(64xTt)^T, scaled by rinv.
// rinv reconstructed inline from g_part. grid (16, 1, BH), 256 thr.
// Writes (t*B+b, h*64+hd) fp16 layout.
// ============================================================================
__global__ void __launch_bounds__(256, 2) av_kernel() {
    extern __shared__ __half sh[];
    __shared__ float siv[128];
    const int bh = blockIdx.z;
    const int m0 = blockIdx.x * 128;

    float acc[2][4][4] = {};
    gemm_nt_f16<64>(g_sh + (size_t)bh * Tt * Tt + (size_t)m0 * Tt,
                    g_vth + (size_t)bh * HDd * Tt, Tt, Tt, Tt,
                    sh, sh + 2 * 128 * 72, acc);

    if (threadIdx.x < 128) {
        const float* p = &g_part[((size_t)bh * Tt + m0 + threadIdx.x) * 32];
        float s = 0.f;
#pragma unroll
        for (int i = 0; i < 32; i++) s += p[i];
        siv[threadIdx.x] = 1.0f / s;
    }
    __syncthreads();

    const int lane = threadIdx.x & 31, g = lane >> 2, q = lane & 3;
    const int w = threadIdx.x >> 5, wm = w & 3, wn = w >> 2;
    const int b = bh >> 4, h = bh & 15;

#pragma unroll
    for (int i = 0; i < 2; i++) {
#pragma unroll
        for (int ch = 0; ch < 2; ch++) {
            const int rl = wm * 32 + i * 16 + ch * 8 + g;
            const int t = m0 + rl;
            const float iv = siv[rl];
#pragma unroll
            for (int j = 0; j < 4; j++) {
                const int col = wn * 32 + j * 8 + q * 2;
                *(__half2*)&g_aoh[((size_t)t * Bb + b) * Ee + h * HDd + col] =
                    __floats2half2_rn(acc[i][j][ch * 2 + 0] * iv,
                                      acc[i][j][ch * 2 + 1] * iv);
            }
        }
    }
}

// ============================================================================
// Kernel 5: out projection -> d_out (fp32). grid (MR/128, Ee/128), 256 thr.
// ============================================================================
__global__ void __launch_bounds__(256, 2) outproj_kernel(const float* __restrict__ ob,
                                                         float* __restrict__ out) {
    extern __shared__ __half sh[];
    const int m0 = blockIdx.x * 128, n0 = blockIdx.y * 128;
    float acc[2][8][4] = {};
    gemm_nt_f16<128>(g_aoh + (size_t)m0 * Ee, g_owh + (size_t)n0 * Ee,
                     Ee, Ee, Ee, sh, sh + 2 * 128 * 72, acc);

    const int lane = threadIdx.x & 31, g = lane >> 2, q = lane & 3;
    const int w = threadIdx.x >> 5, wm = w & 3, wn = w >> 2;

#pragma unroll
    for (int i = 0; i < 2; i++) {
#pragma unroll
        for (int ch = 0; ch < 2; ch++) {
            const int r = m0 + wm * 32 + i * 16 + ch * 8 + g;
#pragma unroll
            for (int j = 0; j < 8; j++) {
                const int o = n0 + wn * 64 + j * 8 + q * 2;
                float2 p = make_float2(acc[i][j][ch * 2 + 0] + ob[o],
                                       acc[i][j][ch * 2 + 1] + ob[o + 1]);
                *(float2*)&out[(size_t)r * Ee + o] = p;
            }
        }
    }
}

// ============================================================================
extern "C" void kernel_launch(void* const* d_in, const int* in_sizes, int n_in,
                              void* d_out, int out_size) {
    const float* query = (const float*)d_in[0];
    const float* key   = (const float*)d_in[1];
    const float* value = (const float*)d_in[2];
    const float* ipw   = (const float*)d_in[3];   // (3E, E)
    const float* ipb   = (const float*)d_in[4];   // (3E,)
    const float* ow    = (const float*)d_in[5];   // (E, E)
    const float* ob    = (const float*)d_in[6];   // (E,)
    // d_in[7..12]: gate params — provably unused (TOPK == E -> all-ones mask).
    (void)in_sizes; (void)n_in; (void)out_size;

    float* out   = (float*)d_out;                     // attn_output (T,B,E)
    float* attnw = out + (size_t)Tt * Bb * Ee;        // attn_weights (B,T,T)

    cudaFuncSetAttribute(qkv_kernel,     cudaFuncAttributeMaxDynamicSharedMemorySize, SMEM_BN128);
    cudaFuncSetAttribute(scores_kernel,  cudaFuncAttributeMaxDynamicSharedMemorySize, SMEM_BN128);
    cudaFuncSetAttribute(av_kernel,      cudaFuncAttributeMaxDynamicSharedMemorySize, SMEM_BN64);
    cudaFuncSetAttribute(outproj_kernel, cudaFuncAttributeMaxDynamicSharedMemorySize, SMEM_BN128);

    prep_kernel    <<<16384, 256>>>(query, key, value, ipw, ow);
    qkv_kernel     <<<dim3(MR / 128, Ee / 128, 3), 256, SMEM_BN128>>>(ipb);
    scores_kernel  <<<dim3(Tt / 128, Tt / 128, BH), 256, SMEM_BN128>>>();
    headmean_kernel<<<Bb * Tt, 512>>>(attnw);
    av_kernel      <<<dim3(Tt / 128, 1, BH), 256, SMEM_BN64>>>();
    outproj_kernel <<<dim3(MR / 128, Ee / 128), 256, SMEM_BN128>>>(ob, out);
}

// round 15
// speedup vs baseline: 1.4626x; 1.0623x over previous
#include <cuda_runtime.h>
#include <cuda_fp16.h>
#include <math.h>
#include <stdint.h>

// Problem constants
#define Tt  2048
#define Bb  2
#define Ee  1024
#define Hh  16
#define HDd 64
#define BH  32          // Bb*Hh
#define MR  4096        // Tt*Bb rows

// -------- device scratch (allocation-free: static device globals) ----------
__device__ __align__(16) __half g_xh[3][(size_t)MR * Ee];    // 24 MB fp16 q/k/v inputs
__device__ __align__(16) __half g_wh[(size_t)3 * Ee * Ee];   //  6 MB fp16 in_proj_w
__device__ __align__(16) __half g_owh[(size_t)Ee * Ee];      //  2 MB fp16 out_w
__device__ __align__(16) __half g_qh[(size_t)BH * Tt * HDd]; //  8 MB (bh,t,hd), q*0.125
__device__ __align__(16) __half g_kh[(size_t)BH * Tt * HDd]; //  8 MB
__device__ __align__(16) __half g_vth[(size_t)BH * HDd * Tt];//  8 MB (bh,hd,t)
__device__ __align__(16) __half g_sh[(size_t)BH * Tt * Tt];  // 256 MB unnormalized exp(scores)
__device__ __align__(16) __half g_aoh[(size_t)MR * Ee];      //  8 MB rows = t*B+b
__device__ __align__(16) float  g_part[(size_t)BH * Tt * 32];//  8 MB rowsum partials

// ============================================================================
// fp16 mma m16n8k16 + ldmatrix + cp.async helpers
// ============================================================================
__device__ __forceinline__ void mma16(float c[4], const uint32_t a[4],
                                      uint32_t b0, uint32_t b1) {
    asm volatile(
        "mma.sync.aligned.m16n8k16.row.col.f32.f16.f16.f32 "
        "{%0,%1,%2,%3}, {%4,%5,%6,%7}, {%8,%9}, {%0,%1,%2,%3};"
        : "+f"(c[0]), "+f"(c[1]), "+f"(c[2]), "+f"(c[3])
        : "r"(a[0]), "r"(a[1]), "r"(a[2]), "r"(a[3]), "r"(b0), "r"(b1));
}
__device__ __forceinline__ void ldsm4(uint32_t r[4], uint32_t addr) {
    asm volatile("ldmatrix.sync.aligned.m8n8.x4.shared.b16 {%0,%1,%2,%3}, [%4];"
        : "=r"(r[0]), "=r"(r[1]), "=r"(r[2]), "=r"(r[3]) : "r"(addr));
}
__device__ __forceinline__ void cpa16(uint32_t dst, const void* src) {
    asm volatile("cp.async.cg.shared.global [%0], [%1], 16;" :: "r"(dst), "l"(src));
}
#define CPA_COMMIT() asm volatile("cp.async.commit_group;" ::: "memory")
#define CPA_WAIT0()  asm volatile("cp.async.wait_group 0;"  ::: "memory")

// ============================================================================
// NT fp16 tensor-core GEMM core, cp.async 2-stage pipeline, K-chunk = 64.
//   C[m,n] += sum_k A[m,k] * B[n,k]   (both K-contiguous row-major, fp16)
// Block 256 thr (8 warps, 4x2). Block tile 128 x BN (64|128). Warp 32 x BN/2.
// Pitch P=72 halves (144B rows): ldmatrix 8-row fetches span all 32 banks.
// One __syncthreads per 64-K chunk.
// ============================================================================
template<int BN>
__device__ __forceinline__ void gemm_nt_f16(
    const __half* __restrict__ A, const __half* __restrict__ B,
    int lda, int ldb, int K, __half* sA, __half* sB,
    float acc[2][BN / 16][4])
{
    constexpr int NT    = BN / 16;
    constexpr int NJJ   = BN / 32;
    constexpr int P     = 72;
    constexpr int ABUFB = 128 * P * 2;        // bytes per A buffer (18432)
    constexpr int BBUFB = BN * P * 2;

    const int tid = threadIdx.x, lane = tid & 31;
    const int w = tid >> 5, wm = w & 3, wn = w >> 2;
    const int lr = lane & 7, sel = lane >> 3;

    const uint32_t sAu = (uint32_t)__cvta_generic_to_shared(sA);
    const uint32_t sBu = (uint32_t)__cvta_generic_to_shared(sB);
    uint32_t aA[2], aB[NJJ];
#pragma unroll
    for (int i = 0; i < 2; i++)
        aA[i] = sAu + (uint32_t)(((wm * 32 + i * 16 + lr + (sel & 1) * 8) * P
                                  + (sel >> 1) * 8) * 2);
#pragma unroll
    for (int jj = 0; jj < NJJ; jj++)
        aB[jj] = sBu + (uint32_t)(((wn * (BN / 2) + jj * 16 + lr + (sel >> 1) * 8) * P
                                   + (sel & 1) * 8) * 2);

    // cp.async mapping: 256 threads cover 32 rows x 64 halves per pass
    const int rA = tid >> 3;                  // 0..31
    const int cA = (tid & 7) * 8;             // halves (16B groups)
    const uint32_t dA = sAu + (uint32_t)((rA * P + cA) * 2);
    const uint32_t dB = sBu + (uint32_t)((rA * P + cA) * 2);
    const __half* Ag = A + (size_t)rA * lda + cA;
    const __half* Bg = B + (size_t)rA * ldb + cA;

#define STAGE_CHUNK(cc, buf) do {                                              \
    const uint32_t _ao = (buf) * ABUFB, _bo = (buf) * BBUFB;                   \
    const __half* _As = Ag + (cc) * 64;                                        \
    const __half* _Bs = Bg + (cc) * 64;                                        \
    _Pragma("unroll")                                                          \
    for (int ii = 0; ii < 4; ii++)                                             \
        cpa16(dA + _ao + ii * (32 * P * 2), _As + (size_t)(ii * 32) * lda);    \
    _Pragma("unroll")                                                          \
    for (int ii = 0; ii < BN / 32; ii++)                                       \
        cpa16(dB + _bo + ii * (32 * P * 2), _Bs + (size_t)(ii * 32) * ldb);    \
    CPA_COMMIT();                                                              \
} while (0)

    STAGE_CHUNK(0, 0);

    const int nch = K / 64;
    for (int c = 0; c < nch; c++) {
        const int p = c & 1;
        CPA_WAIT0();                          // chunk c landed
        __syncthreads();                      // + all warps done with buffer p^1

        if (c + 1 < nch) STAGE_CHUNK(c + 1, p ^ 1);

#pragma unroll
        for (int kb = 0; kb < 4; kb++) {      // four k16 steps per 64-chunk
            uint32_t af[2][4];
            ldsm4(af[0], aA[0] + p * ABUFB + kb * 32);
            ldsm4(af[1], aA[1] + p * ABUFB + kb * 32);
            uint32_t bf[NJJ][4];
#pragma unroll
            for (int jj = 0; jj < NJJ; jj++)
                ldsm4(bf[jj], aB[jj] + p * BBUFB + kb * 32);
#pragma unroll
            for (int j = 0; j < NT; j++) {
                const uint32_t* bp = bf[j >> 1];
                const int o = (j & 1) * 2;
                mma16(acc[0][j], af[0], bp[o], bp[o + 1]);
                mma16(acc[1][j], af[1], bp[o], bp[o + 1]);
            }
        }
    }
    __syncthreads();                          // smem reusable by caller
#undef STAGE_CHUNK
}
// C fragment coords: row = wm*32 + i*16 + ch*8 + g ; col = wn*(BN/2) + j*8 + q*2 (+parity)

#define SMEM_BN128 (2 * (128 * 72 + 128 * 72) * 2)   // 73728 B
#define SMEM_BN64  (2 * (128 * 72 + 64 * 72) * 2)    // 55296 B
#define SMEM_SCORES ((9216 + 2 * 9216 + 17408) * 2)  // Q + 2 K bufs + staging = 90112 B

// ============================================================================
// Kernel 0: fp32 -> fp16 conversion of inputs + weights (one pass).
// Gate params (d_in 7..12) are provably unused: TOPK == E -> all-ones mask,
// so every DGL layer is a plain affine projection.
// ============================================================================
__global__ void prep_kernel(const float* __restrict__ q, const float* __restrict__ k,
                            const float* __restrict__ v, const float* __restrict__ w,
                            const float* __restrict__ ow) {
    const size_t i  = (size_t)blockIdx.x * 256 + threadIdx.x;  // float4 index
    const size_t NX = (size_t)MR * Ee / 4;
    const size_t NW = (size_t)3 * Ee * Ee / 4;
    float4 x; __half* dst;
    if (i < NX)          { x = ((const float4*)q)[i];          dst = g_xh[0] + i * 4; }
    else if (i < 2 * NX) { x = ((const float4*)k)[i - NX];     dst = g_xh[1] + (i - NX) * 4; }
    else if (i < 3 * NX) { x = ((const float4*)v)[i - 2 * NX]; dst = g_xh[2] + (i - 2 * NX) * 4; }
    else if (i < 3 * NX + NW) {
        size_t j = i - 3 * NX;      x = ((const float4*)w)[j];  dst = g_wh + j * 4;
    } else {
        size_t j = i - 3 * NX - NW; x = ((const float4*)ow)[j]; dst = g_owh + j * 4;
    }
    *(__half2*)(dst)     = __floats2half2_rn(x.x, x.y);
    *(__half2*)(dst + 2) = __floats2half2_rn(x.z, x.w);
}

// ============================================================================
// Kernel 1: QKV projection. grid (MR/128, Ee/128, 3), 256 thr.
// V epilogue stages the tile through smem and stores transposed rows
// coalesced (128B runs along t) instead of 2-byte scattered stores.
// ============================================================================
__global__ void __launch_bounds__(256, 2) qkv_kernel(const float* __restrict__ bias) {
    extern __shared__ __half sh[];
    const int mat = blockIdx.z;
    const int m0 = blockIdx.x * 128, n0 = blockIdx.y * 128;
    const float* bp = bias + mat * Ee;

    float acc[2][8][4] = {};
    gemm_nt_f16<128>(g_xh[mat] + (size_t)m0 * Ee,
                     g_wh + (size_t)mat * Ee * Ee + (size_t)n0 * Ee,
                     Ee, Ee, Ee, sh, sh + 2 * 128 * 72, acc);

    const int tid = threadIdx.x;
    const int lane = tid & 31, g = lane >> 2, q = lane & 3;
    const int w = tid >> 5, wm = w & 3, wn = w >> 2;

    if (mat == 2) {
        // stage transposed tile: sT[col][row], pitch 136
        __half* sT = sh;
#pragma unroll
        for (int i = 0; i < 2; i++) {
#pragma unroll
            for (int ch = 0; ch < 2; ch++) {
                const int rl = wm * 32 + i * 16 + ch * 8 + g;
#pragma unroll
                for (int j = 0; j < 8; j++) {
                    const int cl = wn * 64 + j * 8 + q * 2;
                    const int o = n0 + cl;
                    sT[(cl    ) * 136 + rl] = __float2half_rn(acc[i][j][ch * 2 + 0] + bp[o]);
                    sT[(cl + 1) * 136 + rl] = __float2half_rn(acc[i][j][ch * 2 + 1] + bp[o + 1]);
                }
            }
        }
        __syncthreads();
        // one thread per output row (col, b): 64 halves = 128B contiguous in t
        const int col = tid >> 1, b = tid & 1;
        const int oc = n0 + col;
        const int bh = b * Hh + (oc >> 6), hd = oc & 63;
        __half* dst = g_vth + ((size_t)bh * HDd + hd) * Tt + (m0 >> 1);
#pragma unroll
        for (int grp = 0; grp < 8; grp++) {
            __half tmp[8];
#pragma unroll
            for (int e = 0; e < 8; e++)
                tmp[e] = sT[col * 136 + 2 * (grp * 8 + e) + b];
            *(float4*)(dst + grp * 8) = *(const float4*)tmp;
        }
    } else {
#pragma unroll
        for (int i = 0; i < 2; i++) {
#pragma unroll
            for (int ch = 0; ch < 2; ch++) {
                const int r = m0 + wm * 32 + i * 16 + ch * 8 + g;  // = t*B + b
                const int t = r >> 1, b = r & 1;
#pragma unroll
                for (int j = 0; j < 8; j++) {
                    const int o = n0 + wn * 64 + j * 8 + q * 2;
                    float v0 = acc[i][j][ch * 2 + 0] + bp[o];
                    float v1 = acc[i][j][ch * 2 + 1] + bp[o + 1];
                    const int h = o >> 6, hd = o & 63;
                    const int bh = b * Hh + h;
                    if (mat == 0) {
                        *(__half2*)&g_qh[((size_t)bh * Tt + t) * HDd + hd] =
                            __floats2half2_rn(v0 * 0.125f, v1 * 0.125f);
                    } else {
                        *(__half2*)&g_kh[((size_t)bh * Tt + t) * HDd + hd] =
                            __floats2half2_rn(v0, v1);
                    }
                }
            }
        }
    }
}

// ============================================================================
// Kernel 2: scores + exp + rowsum partials. grid (16, 4, BH), 256 thr.
// Block covers 128 rows x 512 cols: Q staged ONCE, K-tiles ping-pong with
// cp.async prefetch under the previous tile's mma + epilogue (hides the
// K=64 GEMM's otherwise fully-exposed load latency).
// Unnormalized exp is safe: logits are O(1).
// ============================================================================
__global__ void __launch_bounds__(256, 2) scores_kernel() {
    extern __shared__ __half sh[];
    constexpr int P = 72;
    constexpr int SQ_H = 128 * P;                    // 9216 halves
    constexpr int KBUFB = 128 * P * 2;               // bytes per K buffer
    __half* sQ = sh;
    __half* sK = sh + SQ_H;
    __half* sS = sh + SQ_H + 2 * SQ_H;               // 128 x 136 staging
    constexpr int PS = 136;

    const int bh = blockIdx.z;
    const int m0 = blockIdx.x * 128;
    const int base_nt = blockIdx.y * 4;              // first of 4 K-tiles

    const int tid = threadIdx.x, lane = tid & 31;
    const int g = lane >> 2, q = lane & 3;
    const int w = tid >> 5, wm = w & 3, wn = w >> 2;
    const int lr = lane & 7, sel = lane >> 3;

    const uint32_t sQu = (uint32_t)__cvta_generic_to_shared(sQ);
    const uint32_t sKu = (uint32_t)__cvta_generic_to_shared(sK);
    uint32_t aQ[2], aK[4];
#pragma unroll
    for (int i = 0; i < 2; i++)
        aQ[i] = sQu + (uint32_t)(((wm * 32 + i * 16 + lr + (sel & 1) * 8) * P
                                  + (sel >> 1) * 8) * 2);
#pragma unroll
    for (int jj = 0; jj < 4; jj++)
        aK[jj] = sKu + (uint32_t)(((wn * 64 + jj * 16 + lr + (sel >> 1) * 8) * P
                                   + (sel & 1) * 8) * 2);

    // cp.async mapping
    const int rA = tid >> 3, cA = (tid & 7) * 8;
    const uint32_t dQ = sQu + (uint32_t)((rA * P + cA) * 2);
    const uint32_t dK = sKu + (uint32_t)((rA * P + cA) * 2);
    const __half* Qg = g_qh + ((size_t)bh * Tt + m0) * HDd;
    const __half* Kg = g_kh + (size_t)bh * Tt * HDd;

    // stage Q (once) + K tile 0
#pragma unroll
    for (int ii = 0; ii < 4; ii++)
        cpa16(dQ + ii * (32 * P * 2), Qg + (size_t)(rA + 32 * ii) * HDd + cA);
#pragma unroll
    for (int ii = 0; ii < 4; ii++)
        cpa16(dK + ii * (32 * P * 2),
              Kg + (size_t)(base_nt * 128 + rA + 32 * ii) * HDd + cA);
    CPA_COMMIT();

    __half* S = g_sh + ((size_t)bh * Tt + m0) * Tt;

    for (int it = 0; it < 4; it++) {
        const int p = it & 1;
        CPA_WAIT0();                          // K tile it (+Q on it=0) landed
        __syncthreads();                      // prior compute/staging reads done

        if (it < 3) {                         // prefetch K tile it+1
#pragma unroll
            for (int ii = 0; ii < 4; ii++)
                cpa16(dK + (p ^ 1) * KBUFB + ii * (32 * P * 2),
                      Kg + (size_t)((base_nt + it + 1) * 128 + rA + 32 * ii) * HDd + cA);
            CPA_COMMIT();
        }

        float acc[2][8][4] = {};
#pragma unroll
        for (int kb = 0; kb < 4; kb++) {
            uint32_t af[2][4];
            ldsm4(af[0], aQ[0] + kb * 32);
            ldsm4(af[1], aQ[1] + kb * 32);
            uint32_t bf[4][4];
#pragma unroll
            for (int jj = 0; jj < 4; jj++)
                ldsm4(bf[jj], aK[jj] + p * KBUFB + kb * 32);
#pragma unroll
            for (int j = 0; j < 8; j++) {
                const uint32_t* bp = bf[j >> 1];
                const int o = (j & 1) * 2;
                mma16(acc[0][j], af[0], bp[o], bp[o + 1]);
                mma16(acc[1][j], af[1], bp[o], bp[o + 1]);
            }
        }

        // exp into staging + rowsum partials
#pragma unroll
        for (int i = 0; i < 2; i++) {
#pragma unroll
            for (int ch = 0; ch < 2; ch++) {
                const int rl = wm * 32 + i * 16 + ch * 8 + g;
                float rs = 0.f;
#pragma unroll
                for (int j = 0; j < 8; j++) {
                    float e0 = __expf(acc[i][j][ch * 2 + 0]);
                    float e1 = __expf(acc[i][j][ch * 2 + 1]);
                    rs += e0 + e1;
                    const int cl = wn * 64 + j * 8 + q * 2;
                    *(__half2*)&sS[rl * PS + cl] = __floats2half2_rn(e0, e1);
                }
                rs += __shfl_xor_sync(0xffffffffu, rs, 1);
                rs += __shfl_xor_sync(0xffffffffu, rs, 2);
                if (q == 0)
                    g_part[((size_t)bh * Tt + m0 + rl) * 32
                           + blockIdx.y * 8 + it * 2 + wn] = rs;
            }
        }
        __syncthreads();

        // coalesced store: 16 threads per row emit 256B runs
        const int n0 = (base_nt + it) * 128;
        const int rr = tid >> 4, cc = (tid & 15) * 8;
#pragma unroll
        for (int st = 0; st < 8; st++) {
            const int r = rr + st * 16;
            *(float4*)&S[(size_t)r * Tt + n0 + cc] = *(const float4*)&sS[r * PS + cc];
        }
    }
}

// ============================================================================
// Kernel 3: attn_weights[b,t,s] = (1/H) sum_h expS[bh,t,s] * rinv[bh,t].
// rinv reconstructed inline from g_part (deterministic 32-float sums).
// ============================================================================
__global__ void headmean_kernel(float* __restrict__ attnw) {
    __shared__ float siv[Hh];
    const int bt = blockIdx.x, b = bt >> 11, t = bt & (Tt - 1);
    if (threadIdx.x < Hh) {
        const float* p = &g_part[((size_t)(b * Hh + threadIdx.x) * Tt + t) * 32];
        float s = 0.f;
#pragma unroll
        for (int i = 0; i < 32; i++) s += p[i];
        siv[threadIdx.x] = 1.0f / s;
    }
    __syncthreads();

    const int c = threadIdx.x;                 // 0..511, 4 halves each
    float4 s = make_float4(0.f, 0.f, 0.f, 0.f);
#pragma unroll
    for (int h = 0; h < Hh; h++) {
        const int bh = b * Hh + h;
        const float iv = siv[h];
        const uint2 raw = ((const uint2*)(g_sh + ((size_t)bh * Tt + t) * Tt))[c];
        const float2 f0 = __half22float2(*(const __half2*)&raw.x);
        const float2 f1 = __half22float2(*(const __half2*)&raw.y);
        s.x += f0.x * iv; s.y += f0.y * iv; s.z += f1.x * iv; s.w += f1.y * iv;
    }
    const float m = 1.0f / (float)Hh;
    s.x *= m; s.y *= m; s.z *= m; s.w *= m;
    ((float4*)(attnw + (size_t)bt * Tt))[c] = s;
}

// ============================================================================
// Kernel 4: AV. D(128x64) = expS(128xTt) . Vt(64xTt)^T, scaled by rinv.
// rinv reconstructed inline from g_part. grid (16, 1, BH), 256 thr.
// ============================================================================
__global__ void __launch_bounds__(256, 2) av_kernel() {
    extern __shared__ __half sh[];
    __shared__ float siv[128];
    const int bh = blockIdx.z;
    const int m0 = blockIdx.x * 128;

    float acc[2][4][4] = {};
    gemm_nt_f16<64>(g_sh + (size_t)bh * Tt * Tt + (size_t)m0 * Tt,
                    g_vth + (size_t)bh * HDd * Tt, Tt, Tt, Tt,
                    sh, sh + 2 * 128 * 72, acc);

    if (threadIdx.x < 128) {
        const float* p = &g_part[((size_t)bh * Tt + m0 + threadIdx.x) * 32];
        float s = 0.f;
#pragma unroll
        for (int i = 0; i < 32; i++) s += p[i];
        siv[threadIdx.x] = 1.0f / s;
    }
    __syncthreads();

    const int lane = threadIdx.x & 31, g = lane >> 2, q = lane & 3;
    const int w = threadIdx.x >> 5, wm = w & 3, wn = w >> 2;
    const int b = bh >> 4, h = bh & 15;

#pragma unroll
    for (int i = 0; i < 2; i++) {
#pragma unroll
        for (int ch = 0; ch < 2; ch++) {
            const int rl = wm * 32 + i * 16 + ch * 8 + g;
            const int t = m0 + rl;
            const float iv = siv[rl];
#pragma unroll
            for (int j = 0; j < 4; j++) {
                const int col = wn * 32 + j * 8 + q * 2;
                *(__half2*)&g_aoh[((size_t)t * Bb + b) * Ee + h * HDd + col] =
                    __floats2half2_rn(acc[i][j][ch * 2 + 0] * iv,
                                      acc[i][j][ch * 2 + 1] * iv);
            }
        }
    }
}

// ============================================================================
// Kernel 5: out projection -> d_out (fp32). grid (MR/128, Ee/128), 256 thr.
// ============================================================================
__global__ void __launch_bounds__(256, 2) outproj_kernel(const float* __restrict__ ob,
                                                         float* __restrict__ out) {
    extern __shared__ __half sh[];
    const int m0 = blockIdx.x * 128, n0 = blockIdx.y * 128;
    float acc[2][8][4] = {};
    gemm_nt_f16<128>(g_aoh + (size_t)m0 * Ee, g_owh + (size_t)n0 * Ee,
                     Ee, Ee, Ee, sh, sh + 2 * 128 * 72, acc);

    const int lane = threadIdx.x & 31, g = lane >> 2, q = lane & 3;
    const int w = threadIdx.x >> 5, wm = w & 3, wn = w >> 2;

#pragma unroll
    for (int i = 0; i < 2; i++) {
#pragma unroll
        for (int ch = 0; ch < 2; ch++) {
            const int r = m0 + wm * 32 + i * 16 + ch * 8 + g;
#pragma unroll
            for (int j = 0; j < 8; j++) {
                const int o = n0 + wn * 64 + j * 8 + q * 2;
                float2 p = make_float2(acc[i][j][ch * 2 + 0] + ob[o],
                                       acc[i][j][ch * 2 + 1] + ob[o + 1]);
                *(float2*)&out[(size_t)r * Ee + o] = p;
            }
        }
    }
}

// ============================================================================
extern "C" void kernel_launch(void* const* d_in, const int* in_sizes, int n_in,
                              void* d_out, int out_size) {
    const float* query = (const float*)d_in[0];
    const float* key   = (const float*)d_in[1];
    const float* value = (const float*)d_in[2];
    const float* ipw   = (const float*)d_in[3];   // (3E, E)
    const float* ipb   = (const float*)d_in[4];   // (3E,)
    const float* ow    = (const float*)d_in[5];   // (E, E)
    const float* ob    = (const float*)d_in[6];   // (E,)
    // d_in[7..12]: gate params — provably unused (TOPK == E -> all-ones mask).
    (void)in_sizes; (void)n_in; (void)out_size;

    float* out   = (float*)d_out;                     // attn_output (T,B,E)
    float* attnw = out + (size_t)Tt * Bb * Ee;        // attn_weights (B,T,T)

    cudaFuncSetAttribute(qkv_kernel,     cudaFuncAttributeMaxDynamicSharedMemorySize, SMEM_BN128);
    cudaFuncSetAttribute(scores_kernel,  cudaFuncAttributeMaxDynamicSharedMemorySize, SMEM_SCORES);
    cudaFuncSetAttribute(av_kernel,      cudaFuncAttributeMaxDynamicSharedMemorySize, SMEM_BN64);
    cudaFuncSetAttribute(outproj_kernel, cudaFuncAttributeMaxDynamicSharedMemorySize, SMEM_BN128);

    prep_kernel    <<<16384, 256>>>(query, key, value, ipw, ow);
    qkv_kernel     <<<dim3(MR / 128, Ee / 128, 3), 256, SMEM_BN128>>>(ipb);
    scores_kernel  <<<dim3(Tt / 128, Tt / 512, BH), 256, SMEM_SCORES>>>();
    headmean_kernel<<<Bb * Tt, 512>>>(attnw);
    av_kernel      <<<dim3(Tt / 128, 1, BH), 256, SMEM_BN64>>>();
    outproj_kernel <<<dim3(MR / 128, Ee / 128), 256, SMEM_BN128>>>(ob, out);
}